// round 7
// baseline (speedup 1.0000x reference)
#include <cuda_runtime.h>
#include <cuda_bf16.h>
#include <cstdint>

typedef unsigned int u32;
typedef unsigned long long u64;

#define HW 16384  // 128*128

// ============================================================================
// Static device scratch
// ============================================================================
__device__ __align__(16) __nv_bfloat16 g_x0h[41 * HW * 128];
__device__ __align__(16) __nv_bfloat16 g_x0l[41 * HW * 128];
__device__ __align__(16) __nv_bfloat16 g_x1h[41 * HW * 64];
__device__ __align__(16) __nv_bfloat16 g_x1l[41 * HW * 64];
__device__ __align__(16) __nv_bfloat16 g_x2h[20 * HW * 64];
__device__ __align__(16) __nv_bfloat16 g_x2l[20 * HW * 64];
__device__ __align__(16) __nv_bfloat16 g_x3h[20 * HW * 64];
__device__ __align__(16) __nv_bfloat16 g_x3l[20 * HW * 64];
__device__ float g_m0[41 * HW];
__device__ float g_m2[20 * HW];
// Weights: per-chunk [64 co][64 ci] bf16, PRE-SWIZZLED (SW128 XOR), hi/lo
__device__ __align__(16) __nv_bfloat16 g_B0h[54 * 4096], g_B0l[54 * 4096];
__device__ __align__(16) __nv_bfloat16 g_B1ah[27 * 4096], g_B1al[27 * 4096];
__device__ __align__(16) __nv_bfloat16 g_B1bh[27 * 4096], g_B1bl[27 * 4096];
__device__ __align__(16) __nv_bfloat16 g_Bd1h[3 * 4096], g_Bd1l[3 * 4096];
__device__ __align__(16) __nv_bfloat16 g_Bd2h[3 * 4096], g_Bd2l[3 * 4096];

// ============================================================================
// PTX helpers
// ============================================================================
__device__ __forceinline__ u32 smem_u32(const void* p) {
    u32 a;
    asm("{ .reg .u64 t; cvta.to.shared.u64 t, %1; cvt.u32.u64 %0, t; }"
        : "=r"(a) : "l"(p));
    return a;
}
__device__ __forceinline__ void cp_async16(u32 dst, const void* src, bool valid) {
    int sz = valid ? 16 : 0;
    asm volatile("cp.async.cg.shared.global [%0], [%1], 16, %2;"
                 :: "r"(dst), "l"(src), "r"(sz) : "memory");
}
__device__ __forceinline__ void cp_commit() {
    asm volatile("cp.async.commit_group;" ::: "memory");
}
template <int N>
__device__ __forceinline__ void cp_wait() {
    asm volatile("cp.async.wait_group %0;" :: "n"(N) : "memory");
}
#define LDMX4(r0, r1, r2, r3, addr) \
    asm volatile("ldmatrix.sync.aligned.m8n8.x4.shared.b16 {%0,%1,%2,%3}, [%4];" \
                 : "=r"(r0), "=r"(r1), "=r"(r2), "=r"(r3) : "r"(addr))

__device__ __forceinline__ void mma_bf16(float* c, const u32* a, const u32* b) {
    asm volatile(
        "mma.sync.aligned.m16n8k16.row.col.f32.bf16.bf16.f32 "
        "{%0,%1,%2,%3}, {%4,%5,%6,%7}, {%8,%9}, {%0,%1,%2,%3};"
        : "+f"(c[0]), "+f"(c[1]), "+f"(c[2]), "+f"(c[3])
        : "r"(a[0]), "r"(a[1]), "r"(a[2]), "r"(a[3]), "r"(b[0]), "r"(b[1]));
}

__device__ __forceinline__ void split_bf16(float v, __nv_bfloat16& h, __nv_bfloat16& l) {
    h = __float2bfloat16_rn(v);
    l = __float2bfloat16_rn(v - __bfloat162float(h));
}
__device__ __forceinline__ int swidx(int co, int ci) {
    int ub = co * 128 + (ci >> 3) * 16;
    int sw = ub ^ ((ub >> 3) & 0x70);
    return (sw >> 1) + (ci & 7);
}
__device__ __forceinline__ u32 swz(u32 b) { return b ^ ((b >> 3) & 0x70); }

// ============================================================================
// Prep kernels
// ============================================================================
__global__ void prep_weights(const float* __restrict__ W0,
                             const float* __restrict__ Wd1,
                             const float* __restrict__ W1a,
                             const float* __restrict__ W1b,
                             const float* __restrict__ Wd2,
                             const float* __restrict__ mask)
{
    const int gid = blockIdx.x * blockDim.x + threadIdx.x;
    const int gs = gridDim.x * blockDim.x;

    for (int i = gid; i < 54 * 4096; i += gs) {
        int chunk = i >> 12, r = i & 4095, co = r >> 6, ci = r & 63;
        int cc = chunk & 1, tap = chunk >> 1;
        int kw = tap % 3, kh = (tap / 3) % 3, kd = tap / 9;
        float v = W0[(size_t)(co * 128 + cc * 64 + ci) * 27 + kd * 9 + kh * 3 + kw];
        __nv_bfloat16 h, l; split_bf16(v, h, l);
        int dst = chunk * 4096 + swidx(co, ci);
        g_B0h[dst] = h; g_B0l[dst] = l;
    }
    for (int i = gid; i < 27 * 4096; i += gs) {
        int chunk = i >> 12, r = i & 4095, co = r >> 6, ci = r & 63;
        int kw = chunk % 3, kh = (chunk / 3) % 3, kd = chunk / 9;
        size_t src = (size_t)(co * 64 + ci) * 27 + kd * 9 + kh * 3 + kw;
        int dst = chunk * 4096 + swidx(co, ci);
        __nv_bfloat16 h, l;
        split_bf16(W1a[src], h, l); g_B1ah[dst] = h; g_B1al[dst] = l;
        split_bf16(W1b[src], h, l); g_B1bh[dst] = h; g_B1bl[dst] = l;
    }
    for (int i = gid; i < 3 * 4096; i += gs) {
        int chunk = i >> 12, r = i & 4095, co = r >> 6, ci = r & 63;
        size_t src = (size_t)(co * 64 + ci) * 3 + chunk;
        int dst = chunk * 4096 + swidx(co, ci);
        __nv_bfloat16 h, l;
        split_bf16(Wd1[src], h, l); g_Bd1h[dst] = h; g_Bd1l[dst] = l;
        split_bf16(Wd2[src], h, l); g_Bd2h[dst] = h; g_Bd2l[dst] = l;
    }
    for (int i = gid; i < 20 * HW; i += gs) {
        int dp = i >> 14, r = i & 16383;
        float a = mask[(size_t)(2 * dp) * HW + r];
        float b = mask[(size_t)(2 * dp + 1) * HW + r];
        float c = mask[(size_t)(2 * dp + 2) * HW + r];
        g_m2[i] = (fmaxf(a, fmaxf(b, c)) > 0.5f) ? 1.0f : 0.0f;
    }
}

__global__ void __launch_bounds__(256) conv0_pre(const float* __restrict__ feat,
                                                 const float* __restrict__ mask)
{
    const int h = blockIdx.x, d = blockIdx.y;
    const int tid = threadIdx.x;
    __shared__ float t[32][129];
    __shared__ float mrow[128];

    const size_t row0 = ((size_t)d * 128 + h) * 128;
    if (tid < 128) {
        float mv = mask[row0 + tid] > 0.5f ? 1.0f : 0.0f;
        mrow[tid] = mv;
        g_m0[row0 + tid] = mv;
    }
    __syncthreads();

    for (int cc = 0; cc < 4; ++cc) {
        #pragma unroll 1
        for (int i = tid; i < 32 * 128; i += 256) {
            int ci = i >> 7, w = i & 127;
            t[ci][w] = feat[((size_t)(cc * 32 + ci) * 41 + d) * HW + h * 128 + w];
        }
        __syncthreads();
        #pragma unroll 1
        for (int i = tid; i < 128 * 16; i += 256) {
            int w = i >> 4, p = i & 15;
            float mv = mrow[w];
            float v0 = t[p * 2][w] * mv;
            float v1 = t[p * 2 + 1][w] * mv;
            __nv_bfloat16 h0, l0, h1, l1;
            split_bf16(v0, h0, l0);
            split_bf16(v1, h1, l1);
            __nv_bfloat162 hh(h0, h1), ll(l0, l1);
            size_t base = (row0 + w) * 128 + cc * 32;
            *(__nv_bfloat162*)(g_x0h + base + p * 2) = hh;
            *(__nv_bfloat162*)(g_x0l + base + p * 2) = ll;
        }
        __syncthreads();
    }
}

// ============================================================================
// Unified implicit-GEMM conv (mma.sync), bf16 hi/lo split with 3 INDEPENDENT
// accumulator sets (hh / hl / lh) to break serial HMMA chains.
// 512 threads, 16 warps: warp_m = wid&7 (m16), warp_n = wid>>3 (n32).
// K333: A staged once per (kd,kh,cc) with w-halo; kw = ldmatrix row shift.
// !K333 (down, stride-2 d): 3 stages (kd), no halo, KW=1.
// ============================================================================
template <int CC, bool K333, bool OMASK, bool FP32OUT>
__global__ void __launch_bounds__(512)
conv_mma_kernel(const __nv_bfloat16* __restrict__ in_hi,
                const __nv_bfloat16* __restrict__ in_lo,
                const __nv_bfloat16* __restrict__ w_hi,
                const __nv_bfloat16* __restrict__ w_lo,
                const float* __restrict__ omask,
                __nv_bfloat16* __restrict__ out_hi,
                __nv_bfloat16* __restrict__ out_lo,
                float* __restrict__ out_f32,
                int Din, int Dout)
{
    constexpr int KW = K333 ? 3 : 1;
    constexpr int AROWS = K333 ? 130 : 128;
    constexpr int A_SPLIT = K333 ? 16896 : 16384;
    constexpr int STAGE_A = 2 * A_SPLIT;
    constexpr int STAGE_B = KW * 16384;
    constexpr int STAGEB = STAGE_A + STAGE_B;

    extern __shared__ char smem[];
    const u32 smem_base = smem_u32(smem);
    const int tid = threadIdx.x;
    const int wid = tid >> 5;
    const int lane = tid & 31;
    const int h = blockIdx.x;
    const int dz = blockIdx.y;
    const int CITOT = CC * 64;
    const int warp_m = wid & 7;
    const int warp_n = wid >> 3;

    __shared__ int s_din[18];
    __shared__ int s_aux[18];   // hin | cc<<8 | wbase<<12
    __shared__ int s_n;
    __shared__ float s_mask[128];

    if (tid == 0) {
        int n = 0;
        if (K333) {
            for (int kd = 0; kd < 3; ++kd) {
                int din = dz + kd - 1;
                if (din < 0 || din >= Din) continue;
                for (int kh = 0; kh < 3; ++kh) {
                    int hin = h + kh - 1;
                    if ((unsigned)hin > 127u) continue;
                    for (int cc = 0; cc < CC; ++cc) {
                        int wbase = ((kd * 3 + kh) * 3) * CC + cc;
                        s_din[n] = din;
                        s_aux[n] = hin | (cc << 8) | (wbase << 12);
                        ++n;
                    }
                }
            }
        } else {
            for (int kd = 0; kd < 3; ++kd) {
                s_din[n] = 2 * dz + kd;
                s_aux[n] = h | (kd << 12);
                ++n;
            }
        }
        s_n = n;
    }
    if (OMASK && tid < 128)
        s_mask[tid] = omask[((size_t)dz * 128 + h) * 128 + tid];
    __syncthreads();
    const int nch = s_n;

    // A ldmatrix addressing (stored row = m + kw for K333 halo; = m for down)
    u32 a_rowk[KW], a_sxk[KW];
    {
        int r = warp_m * 16 + (lane & 7) + ((lane >> 3) & 1) * 8;
        #pragma unroll
        for (int kw = 0; kw < KW; ++kw) {
            a_rowk[kw] = (u32)(r + kw) * 128;
            a_sxk[kw] = (u32)((r + kw) & 7) << 4;
        }
    }
    const u32 a_c = (u32)(lane >> 4) * 16;

    u32 b_row[2], b_sx[2];
    #pragma unroll
    for (int nh = 0; nh < 2; ++nh) {
        int rown = warp_n * 32 + nh * 16 + (lane & 7) + (lane >> 4) * 8;
        b_row[nh] = (u32)rown * 128;
        b_sx[nh] = (u32)(rown & 7) << 4;
    }
    const u32 b_c = (u32)((lane >> 3) & 1) * 16;

    // 3 independent accumulator sets -> no serial HMMA chains
    float acc_hh[4][4], acc_hl[4][4], acc_lh[4][4];
    #pragma unroll
    for (int nt = 0; nt < 4; ++nt)
        #pragma unroll
        for (int q = 0; q < 4; ++q) {
            acc_hh[nt][q] = 0.0f; acc_hl[nt][q] = 0.0f; acc_lh[nt][q] = 0.0f;
        }

    // ---- staging ----
    auto stage = [&](int i, int buf) {
        const int din = s_din[i];
        const int aux = s_aux[i];
        const int hin = aux & 255;
        const int cc = (aux >> 8) & 15;
        const int wb = aux >> 12;
        const u32 base = smem_base + (u32)buf * STAGEB;
        #pragma unroll 1
        for (int t = tid; t < AROWS * 8 * 2; t += 512) {
            int sp2 = t >= AROWS * 8;
            int u = sp2 ? t - AROWS * 8 : t;
            int row = u >> 3, seg = u & 7;
            int win = K333 ? row - 1 : row;
            bool valid = !K333 || (unsigned)win < 128u;
            const char* src = (const char*)((sp2 ? in_lo : in_hi) +
                (((size_t)din * 128 + hin) * 128 + (valid ? win : 0)) * CITOT +
                cc * 64) + seg * 16;
            cp_async16(base + sp2 * A_SPLIT + swz(row * 128 + seg * 16), src, valid);
        }
        #pragma unroll 1
        for (int t = tid; t < KW * 1024; t += 512) {
            int tile = t >> 9, idx = t & 511;
            int kw = tile >> 1, sp2 = tile & 1;
            const char* src = (const char*)((sp2 ? w_lo : w_hi) +
                (size_t)(wb + kw * CC) * 4096) + idx * 16;
            cp_async16(base + STAGE_A + kw * 16384 + sp2 * 8192 + idx * 16, src, true);
        }
        cp_commit();
    };

    stage(0, 0);
    for (int i = 0; i < nch; ++i) {
        const int buf = i & 1;
        if (i + 1 < nch) { stage(i + 1, buf ^ 1); cp_wait<1>(); }
        else             { cp_wait<0>(); }
        __syncthreads();

        const u32 ahi = smem_base + (u32)buf * STAGEB;
        const u32 alo = ahi + A_SPLIT;
        const u32 bb = ahi + STAGE_A;

        #pragma unroll
        for (int kw = 0; kw < KW; ++kw) {
            const u32 bhi = bb + kw * 16384;
            const u32 blo = bhi + 8192;
            #pragma unroll
            for (int k16 = 0; k16 < 4; ++k16) {
                const u32 ko = k16 * 32;
                const u32 aoff = a_rowk[kw] + ((a_c + ko) ^ a_sxk[kw]);
                u32 A0[4], A1[4];
                LDMX4(A0[0], A0[1], A0[2], A0[3], ahi + aoff);
                LDMX4(A1[0], A1[1], A1[2], A1[3], alo + aoff);
                u32 B0[4][2], B1[4][2];
                #pragma unroll
                for (int nh = 0; nh < 2; ++nh) {
                    const u32 boff = b_row[nh] + ((b_c + ko) ^ b_sx[nh]);
                    LDMX4(B0[2*nh][0], B0[2*nh][1], B0[2*nh+1][0], B0[2*nh+1][1],
                          bhi + boff);
                    LDMX4(B1[2*nh][0], B1[2*nh][1], B1[2*nh+1][0], B1[2*nh+1][1],
                          blo + boff);
                }
                #pragma unroll
                for (int nt = 0; nt < 4; ++nt) {
                    mma_bf16(acc_hh[nt], A0, B0[nt]);
                    mma_bf16(acc_hl[nt], A0, B1[nt]);
                    mma_bf16(acc_lh[nt], A1, B0[nt]);
                }
            }
        }
        __syncthreads();
    }

    // ---- epilogue ----
    const int g = lane >> 2, tg = lane & 3;
    #pragma unroll
    for (int half = 0; half < 2; ++half) {
        const int m = warp_m * 16 + g + half * 8;
        const float mv = OMASK ? s_mask[m] : 1.0f;
        const size_t row = ((size_t)dz * 128 + h) * 128 + m;
        #pragma unroll
        for (int nt = 0; nt < 4; ++nt) {
            const int n0 = warp_n * 32 + nt * 8 + tg * 2;
            const int q0 = half * 2;
            float v0 = (acc_hh[nt][q0]   + acc_hl[nt][q0])   + acc_lh[nt][q0];
            float v1 = (acc_hh[nt][q0+1] + acc_hl[nt][q0+1]) + acc_lh[nt][q0+1];
            v0 = fmaxf(v0 * mv, 0.0f);
            v1 = fmaxf(v1 * mv, 0.0f);
            if (FP32OUT) {
                out_f32[((size_t)n0 * Dout + dz) * HW + h * 128 + m] = v0;
                out_f32[((size_t)(n0 + 1) * Dout + dz) * HW + h * 128 + m] = v1;
            } else {
                __nv_bfloat16 h0, l0, h1, l1;
                split_bf16(v0, h0, l0);
                split_bf16(v1, h1, l1);
                __nv_bfloat162 hh(h0, h1), ll(l0, l1);
                *(u32*)(out_hi + row * 64 + n0) = *(u32*)&hh;
                *(u32*)(out_lo + row * 64 + n0) = *(u32*)&ll;
            }
        }
    }
}

#define SMEM_SUBM (2 * (2 * 16896 + 3 * 16384))   // 165888
#define SMEM_DOWN (2 * (2 * 16384 + 1 * 16384))   // 98304

// ============================================================================
extern "C" void kernel_launch(void* const* d_in, const int* in_sizes, int n_in,
                              void* d_out, int out_size)
{
    const float* feat = (const float*)d_in[0];
    const float* mask = (const float*)d_in[1];
    const float* W0   = (const float*)d_in[2];
    const float* Wd1  = (const float*)d_in[3];
    const float* W1a  = (const float*)d_in[4];
    const float* W1b  = (const float*)d_in[5];
    const float* Wd2  = (const float*)d_in[6];
    float* out = (float*)d_out;

    void* p;
    #define SYM(v, s) cudaGetSymbolAddress(&p, s); auto* v = (decltype(&s[0]))p;
    SYM(x0h, g_x0h) SYM(x0l, g_x0l)
    SYM(x1h, g_x1h) SYM(x1l, g_x1l)
    SYM(x2h, g_x2h) SYM(x2l, g_x2l)
    SYM(x3h, g_x3h) SYM(x3l, g_x3l)
    SYM(m0, g_m0)   SYM(m2, g_m2)
    SYM(b0h, g_B0h)   SYM(b0l, g_B0l)
    SYM(b1ah, g_B1ah) SYM(b1al, g_B1al)
    SYM(b1bh, g_B1bh) SYM(b1bl, g_B1bl)
    SYM(bd1h, g_Bd1h) SYM(bd1l, g_Bd1l)
    SYM(bd2h, g_Bd2h) SYM(bd2l, g_Bd2l)
    #undef SYM

    cudaFuncSetAttribute(conv_mma_kernel<2, true, true, false>,
                         cudaFuncAttributeMaxDynamicSharedMemorySize, SMEM_SUBM);
    cudaFuncSetAttribute(conv_mma_kernel<1, true, true, false>,
                         cudaFuncAttributeMaxDynamicSharedMemorySize, SMEM_SUBM);
    cudaFuncSetAttribute(conv_mma_kernel<1, false, false, false>,
                         cudaFuncAttributeMaxDynamicSharedMemorySize, SMEM_DOWN);
    cudaFuncSetAttribute(conv_mma_kernel<1, false, false, true>,
                         cudaFuncAttributeMaxDynamicSharedMemorySize, SMEM_DOWN);

    prep_weights<<<264, 256>>>(W0, Wd1, W1a, W1b, Wd2, mask);
    conv0_pre<<<dim3(128, 41), 256>>>(feat, mask);

    // conv0: 128->64, 3x3x3 SAME, output masked by m0 (input pre-masked)
    conv_mma_kernel<2, true, true, false><<<dim3(128, 41), 512, SMEM_SUBM>>>(
        x0h, x0l, b0h, b0l, m0, x1h, x1l, nullptr, 41, 41);
    // down1: (3,1,1)/stride(2,1,1), relu
    conv_mma_kernel<1, false, false, false><<<dim3(128, 20), 512, SMEM_DOWN>>>(
        x1h, x1l, bd1h, bd1l, nullptr, x2h, x2l, nullptr, 41, 20);
    // subm1a / subm1b: 3x3x3 SAME, output masked by m2
    conv_mma_kernel<1, true, true, false><<<dim3(128, 20), 512, SMEM_SUBM>>>(
        x2h, x2l, b1ah, b1al, m2, x3h, x3l, nullptr, 20, 20);
    conv_mma_kernel<1, true, true, false><<<dim3(128, 20), 512, SMEM_SUBM>>>(
        x3h, x3l, b1bh, b1bl, m2, x1h, x1l, nullptr, 20, 20);
    // down2 -> fp32 NCDHW output
    conv_mma_kernel<1, false, false, true><<<dim3(128, 9), 512, SMEM_DOWN>>>(
        x1h, x1l, bd2h, bd2l, nullptr, nullptr, nullptr, out, 20, 9);
}

// round 8
// speedup vs baseline: 1.2655x; 1.2655x over previous
#include <cuda_runtime.h>
#include <cuda_fp16.h>
#include <cstdint>

typedef unsigned int u32;
typedef unsigned long long u64;

#define HW 16384  // 128*128

// ============================================================================
// Static device scratch — activations single fp16, channels-last [d][h][w][ci]
// ============================================================================
__device__ __align__(16) __half g_x0[41 * HW * 128];
__device__ __align__(16) __half g_x1[41 * HW * 64];
__device__ __align__(16) __half g_x2[20 * HW * 64];
__device__ __align__(16) __half g_x3[20 * HW * 64];
__device__ float g_m0[41 * HW];
__device__ float g_m2[20 * HW];
// Weights: per-chunk [64 co][64 ci] fp16, PRE-SWIZZLED (SW128 XOR), hi/lo
__device__ __align__(16) __half g_B0h[54 * 4096], g_B0l[54 * 4096];
__device__ __align__(16) __half g_B1ah[27 * 4096], g_B1al[27 * 4096];
__device__ __align__(16) __half g_B1bh[27 * 4096], g_B1bl[27 * 4096];
__device__ __align__(16) __half g_Bd1h[3 * 4096], g_Bd1l[3 * 4096];
__device__ __align__(16) __half g_Bd2h[3 * 4096], g_Bd2l[3 * 4096];

// ============================================================================
// PTX helpers
// ============================================================================
__device__ __forceinline__ u32 smem_u32(const void* p) {
    u32 a;
    asm("{ .reg .u64 t; cvta.to.shared.u64 t, %1; cvt.u32.u64 %0, t; }"
        : "=r"(a) : "l"(p));
    return a;
}
__device__ __forceinline__ void cp_async16(u32 dst, const void* src, bool valid) {
    int sz = valid ? 16 : 0;
    asm volatile("cp.async.cg.shared.global [%0], [%1], 16, %2;"
                 :: "r"(dst), "l"(src), "r"(sz) : "memory");
}
__device__ __forceinline__ void cp_commit() {
    asm volatile("cp.async.commit_group;" ::: "memory");
}
template <int N>
__device__ __forceinline__ void cp_wait() {
    asm volatile("cp.async.wait_group %0;" :: "n"(N) : "memory");
}
#define LDMX4(r0, r1, r2, r3, addr) \
    asm volatile("ldmatrix.sync.aligned.m8n8.x4.shared.b16 {%0,%1,%2,%3}, [%4];" \
                 : "=r"(r0), "=r"(r1), "=r"(r2), "=r"(r3) : "r"(addr))

__device__ __forceinline__ void mma_f16(float* c, const u32* a, const u32* b) {
    asm volatile(
        "mma.sync.aligned.m16n8k16.row.col.f32.f16.f16.f32 "
        "{%0,%1,%2,%3}, {%4,%5,%6,%7}, {%8,%9}, {%0,%1,%2,%3};"
        : "+f"(c[0]), "+f"(c[1]), "+f"(c[2]), "+f"(c[3])
        : "r"(a[0]), "r"(a[1]), "r"(a[2]), "r"(a[3]), "r"(b[0]), "r"(b[1]));
}

__device__ __forceinline__ void split_f16(float v, __half& h, __half& l) {
    h = __float2half_rn(v);
    l = __float2half_rn(v - __half2float(h));
}
__device__ __forceinline__ int swidx(int co, int ci) {
    int ub = co * 128 + (ci >> 3) * 16;
    int sw = ub ^ ((ub >> 3) & 0x70);
    return (sw >> 1) + (ci & 7);
}
__device__ __forceinline__ u32 swz(u32 b) { return b ^ ((b >> 3) & 0x70); }

// ============================================================================
// Prep kernels
// ============================================================================
__global__ void prep_weights(const float* __restrict__ W0,
                             const float* __restrict__ Wd1,
                             const float* __restrict__ W1a,
                             const float* __restrict__ W1b,
                             const float* __restrict__ Wd2,
                             const float* __restrict__ mask)
{
    const int gid = blockIdx.x * blockDim.x + threadIdx.x;
    const int gs = gridDim.x * blockDim.x;

    for (int i = gid; i < 54 * 4096; i += gs) {
        int chunk = i >> 12, r = i & 4095, co = r >> 6, ci = r & 63;
        int cc = chunk & 1, tap = chunk >> 1;
        int kw = tap % 3, kh = (tap / 3) % 3, kd = tap / 9;
        float v = W0[(size_t)(co * 128 + cc * 64 + ci) * 27 + kd * 9 + kh * 3 + kw];
        __half h, l; split_f16(v, h, l);
        int dst = chunk * 4096 + swidx(co, ci);
        g_B0h[dst] = h; g_B0l[dst] = l;
    }
    for (int i = gid; i < 27 * 4096; i += gs) {
        int chunk = i >> 12, r = i & 4095, co = r >> 6, ci = r & 63;
        int kw = chunk % 3, kh = (chunk / 3) % 3, kd = chunk / 9;
        size_t src = (size_t)(co * 64 + ci) * 27 + kd * 9 + kh * 3 + kw;
        int dst = chunk * 4096 + swidx(co, ci);
        __half h, l;
        split_f16(W1a[src], h, l); g_B1ah[dst] = h; g_B1al[dst] = l;
        split_f16(W1b[src], h, l); g_B1bh[dst] = h; g_B1bl[dst] = l;
    }
    for (int i = gid; i < 3 * 4096; i += gs) {
        int chunk = i >> 12, r = i & 4095, co = r >> 6, ci = r & 63;
        size_t src = (size_t)(co * 64 + ci) * 3 + chunk;
        int dst = chunk * 4096 + swidx(co, ci);
        __half h, l;
        split_f16(Wd1[src], h, l); g_Bd1h[dst] = h; g_Bd1l[dst] = l;
        split_f16(Wd2[src], h, l); g_Bd2h[dst] = h; g_Bd2l[dst] = l;
    }
    for (int i = gid; i < 20 * HW; i += gs) {
        int dp = i >> 14, r = i & 16383;
        float a = mask[(size_t)(2 * dp) * HW + r];
        float b = mask[(size_t)(2 * dp + 1) * HW + r];
        float c = mask[(size_t)(2 * dp + 2) * HW + r];
        g_m2[i] = (fmaxf(a, fmaxf(b, c)) > 0.5f) ? 1.0f : 0.0f;
    }
}

__global__ void __launch_bounds__(256) conv0_pre(const float* __restrict__ feat,
                                                 const float* __restrict__ mask)
{
    const int h = blockIdx.x, d = blockIdx.y;
    const int tid = threadIdx.x;
    __shared__ float t[32][129];
    __shared__ float mrow[128];

    const size_t row0 = ((size_t)d * 128 + h) * 128;
    if (tid < 128) {
        float mv = mask[row0 + tid] > 0.5f ? 1.0f : 0.0f;
        mrow[tid] = mv;
        g_m0[row0 + tid] = mv;
    }
    __syncthreads();

    for (int cc = 0; cc < 4; ++cc) {
        #pragma unroll 1
        for (int i = tid; i < 32 * 128; i += 256) {
            int ci = i >> 7, w = i & 127;
            t[ci][w] = feat[((size_t)(cc * 32 + ci) * 41 + d) * HW + h * 128 + w];
        }
        __syncthreads();
        #pragma unroll 1
        for (int i = tid; i < 128 * 16; i += 256) {
            int w = i >> 4, p = i & 15;
            float mv = mrow[w];
            float v0 = t[p * 2][w] * mv;
            float v1 = t[p * 2 + 1][w] * mv;
            __half2 hv(__float2half_rn(v0), __float2half_rn(v1));
            size_t base = (row0 + w) * 128 + cc * 32;
            *(__half2*)(g_x0 + base + p * 2) = hv;
        }
        __syncthreads();
    }
}

// ============================================================================
// Unified implicit-GEMM conv (mma.sync fp16), 2-term split:
//   out = Ah·(Bh + Bl)  — A single fp16, B weights split hi/lo.
// 512 threads, 16 warps: warp_m = wid&7 (m16), warp_n = wid>>3 (n32).
// K333: A staged once per (kd,kh,cc) with w-halo; kw = ldmatrix row shift.
// ============================================================================
template <int CC, bool K333, bool OMASK, bool FP32OUT>
__global__ void __launch_bounds__(512)
conv_mma_kernel(const __half* __restrict__ in,
                const __half* __restrict__ w_hi,
                const __half* __restrict__ w_lo,
                const float* __restrict__ omask,
                __half* __restrict__ out,
                float* __restrict__ out_f32,
                int Din, int Dout)
{
    constexpr int KW = K333 ? 3 : 1;
    constexpr int AROWS = K333 ? 130 : 128;
    constexpr int STAGE_A = K333 ? 16896 : 16384;
    constexpr int STAGE_B = KW * 16384;
    constexpr int STAGEB = STAGE_A + STAGE_B;

    extern __shared__ char smem[];
    const u32 smem_base = smem_u32(smem);
    const int tid = threadIdx.x;
    const int wid = tid >> 5;
    const int lane = tid & 31;
    const int h = blockIdx.x;
    const int dz = blockIdx.y;
    const int CITOT = CC * 64;
    const int warp_m = wid & 7;
    const int warp_n = wid >> 3;

    __shared__ int s_din[18];
    __shared__ int s_aux[18];   // hin | cc<<8 | wbase<<12
    __shared__ int s_n;
    __shared__ float s_mask[128];

    if (tid == 0) {
        int n = 0;
        if (K333) {
            for (int kd = 0; kd < 3; ++kd) {
                int din = dz + kd - 1;
                if (din < 0 || din >= Din) continue;
                for (int kh = 0; kh < 3; ++kh) {
                    int hin = h + kh - 1;
                    if ((unsigned)hin > 127u) continue;
                    for (int cc = 0; cc < CC; ++cc) {
                        int wbase = ((kd * 3 + kh) * 3) * CC + cc;
                        s_din[n] = din;
                        s_aux[n] = hin | (cc << 8) | (wbase << 12);
                        ++n;
                    }
                }
            }
        } else {
            for (int kd = 0; kd < 3; ++kd) {
                s_din[n] = 2 * dz + kd;
                s_aux[n] = h | (kd << 12);
                ++n;
            }
        }
        s_n = n;
    }
    if (OMASK && tid < 128)
        s_mask[tid] = omask[((size_t)dz * 128 + h) * 128 + tid];
    __syncthreads();
    const int nch = s_n;

    // A ldmatrix addressing (stored row = m + kw for K333 halo; = m for down)
    u32 a_rowk[KW], a_sxk[KW];
    {
        int r = warp_m * 16 + (lane & 7) + ((lane >> 3) & 1) * 8;
        #pragma unroll
        for (int kw = 0; kw < KW; ++kw) {
            a_rowk[kw] = (u32)(r + kw) * 128;
            a_sxk[kw] = (u32)((r + kw) & 7) << 4;
        }
    }
    const u32 a_c = (u32)(lane >> 4) * 16;

    u32 b_row[2], b_sx[2];
    #pragma unroll
    for (int nh = 0; nh < 2; ++nh) {
        int rown = warp_n * 32 + nh * 16 + (lane & 7) + (lane >> 4) * 8;
        b_row[nh] = (u32)rown * 128;
        b_sx[nh] = (u32)(rown & 7) << 4;
    }
    const u32 b_c = (u32)((lane >> 3) & 1) * 16;

    // 2 independent accumulator sets (hi·hi, hi·lo)
    float acc_hh[4][4], acc_hl[4][4];
    #pragma unroll
    for (int nt = 0; nt < 4; ++nt)
        #pragma unroll
        for (int q = 0; q < 4; ++q) { acc_hh[nt][q] = 0.0f; acc_hl[nt][q] = 0.0f; }

    // ---- staging ----
    auto stage = [&](int i, int buf) {
        const int din = s_din[i];
        const int aux = s_aux[i];
        const int hin = aux & 255;
        const int cc = (aux >> 8) & 15;
        const int wb = aux >> 12;
        const u32 base = smem_base + (u32)buf * STAGEB;
        #pragma unroll 1
        for (int t = tid; t < AROWS * 8; t += 512) {
            int row = t >> 3, seg = t & 7;
            int win = K333 ? row - 1 : row;
            bool valid = !K333 || (unsigned)win < 128u;
            const char* src = (const char*)(in +
                (((size_t)din * 128 + hin) * 128 + (valid ? win : 0)) * CITOT +
                cc * 64) + seg * 16;
            cp_async16(base + swz(row * 128 + seg * 16), src, valid);
        }
        #pragma unroll 1
        for (int t = tid; t < KW * 1024; t += 512) {
            int tile = t >> 9, idx = t & 511;
            int kw = tile >> 1, sp2 = tile & 1;
            const char* src = (const char*)((sp2 ? w_lo : w_hi) +
                (size_t)(wb + kw * CC) * 4096) + idx * 16;
            cp_async16(base + STAGE_A + kw * 16384 + sp2 * 8192 + idx * 16, src, true);
        }
        cp_commit();
    };

    stage(0, 0);
    for (int i = 0; i < nch; ++i) {
        const int buf = i & 1;
        if (i + 1 < nch) { stage(i + 1, buf ^ 1); cp_wait<1>(); }
        else             { cp_wait<0>(); }
        __syncthreads();

        const u32 ab = smem_base + (u32)buf * STAGEB;
        const u32 bb = ab + STAGE_A;

        #pragma unroll
        for (int kw = 0; kw < KW; ++kw) {
            const u32 bhi = bb + kw * 16384;
            const u32 blo = bhi + 8192;
            #pragma unroll
            for (int k16 = 0; k16 < 4; ++k16) {
                const u32 ko = k16 * 32;
                const u32 aoff = a_rowk[kw] + ((a_c + ko) ^ a_sxk[kw]);
                u32 A[4];
                LDMX4(A[0], A[1], A[2], A[3], ab + aoff);
                u32 B0[4][2], B1[4][2];
                #pragma unroll
                for (int nh = 0; nh < 2; ++nh) {
                    const u32 boff = b_row[nh] + ((b_c + ko) ^ b_sx[nh]);
                    LDMX4(B0[2*nh][0], B0[2*nh][1], B0[2*nh+1][0], B0[2*nh+1][1],
                          bhi + boff);
                    LDMX4(B1[2*nh][0], B1[2*nh][1], B1[2*nh+1][0], B1[2*nh+1][1],
                          blo + boff);
                }
                #pragma unroll
                for (int nt = 0; nt < 4; ++nt) {
                    mma_f16(acc_hh[nt], A, B0[nt]);
                    mma_f16(acc_hl[nt], A, B1[nt]);
                }
            }
        }
        __syncthreads();
    }

    // ---- epilogue ----
    const int g = lane >> 2, tg = lane & 3;
    #pragma unroll
    for (int half = 0; half < 2; ++half) {
        const int m = warp_m * 16 + g + half * 8;
        const float mv = OMASK ? s_mask[m] : 1.0f;
        const size_t row = ((size_t)dz * 128 + h) * 128 + m;
        #pragma unroll
        for (int nt = 0; nt < 4; ++nt) {
            const int n0 = warp_n * 32 + nt * 8 + tg * 2;
            const int q0 = half * 2;
            float v0 = acc_hh[nt][q0]   + acc_hl[nt][q0];
            float v1 = acc_hh[nt][q0+1] + acc_hl[nt][q0+1];
            v0 = fmaxf(v0 * mv, 0.0f);
            v1 = fmaxf(v1 * mv, 0.0f);
            if (FP32OUT) {
                out_f32[((size_t)n0 * Dout + dz) * HW + h * 128 + m] = v0;
                out_f32[((size_t)(n0 + 1) * Dout + dz) * HW + h * 128 + m] = v1;
            } else {
                __half2 hv(__float2half_rn(v0), __float2half_rn(v1));
                *(u32*)(out + row * 64 + n0) = *(u32*)&hv;
            }
        }
    }
}

#define SMEM_SUBM (2 * (16896 + 3 * 16384))   // 132096
#define SMEM_DOWN (2 * (16384 + 1 * 16384))   // 65536

// ============================================================================
extern "C" void kernel_launch(void* const* d_in, const int* in_sizes, int n_in,
                              void* d_out, int out_size)
{
    const float* feat = (const float*)d_in[0];
    const float* mask = (const float*)d_in[1];
    const float* W0   = (const float*)d_in[2];
    const float* Wd1  = (const float*)d_in[3];
    const float* W1a  = (const float*)d_in[4];
    const float* W1b  = (const float*)d_in[5];
    const float* Wd2  = (const float*)d_in[6];
    float* out = (float*)d_out;

    void* p;
    #define SYM(v, s) cudaGetSymbolAddress(&p, s); auto* v = (decltype(&s[0]))p;
    SYM(x0, g_x0) SYM(x1, g_x1) SYM(x2, g_x2) SYM(x3, g_x3)
    SYM(m0, g_m0) SYM(m2, g_m2)
    SYM(b0h, g_B0h)   SYM(b0l, g_B0l)
    SYM(b1ah, g_B1ah) SYM(b1al, g_B1al)
    SYM(b1bh, g_B1bh) SYM(b1bl, g_B1bl)
    SYM(bd1h, g_Bd1h) SYM(bd1l, g_Bd1l)
    SYM(bd2h, g_Bd2h) SYM(bd2l, g_Bd2l)
    #undef SYM

    cudaFuncSetAttribute(conv_mma_kernel<2, true, true, false>,
                         cudaFuncAttributeMaxDynamicSharedMemorySize, SMEM_SUBM);
    cudaFuncSetAttribute(conv_mma_kernel<1, true, true, false>,
                         cudaFuncAttributeMaxDynamicSharedMemorySize, SMEM_SUBM);
    cudaFuncSetAttribute(conv_mma_kernel<1, false, false, false>,
                         cudaFuncAttributeMaxDynamicSharedMemorySize, SMEM_DOWN);
    cudaFuncSetAttribute(conv_mma_kernel<1, false, false, true>,
                         cudaFuncAttributeMaxDynamicSharedMemorySize, SMEM_DOWN);

    prep_weights<<<264, 256>>>(W0, Wd1, W1a, W1b, Wd2, mask);
    conv0_pre<<<dim3(128, 41), 256>>>(feat, mask);

    // conv0: 128->64, 3x3x3 SAME, output masked by m0 (input pre-masked)
    conv_mma_kernel<2, true, true, false><<<dim3(128, 41), 512, SMEM_SUBM>>>(
        x0, b0h, b0l, m0, x1, nullptr, 41, 41);
    // down1: (3,1,1)/stride(2,1,1), relu
    conv_mma_kernel<1, false, false, false><<<dim3(128, 20), 512, SMEM_DOWN>>>(
        x1, bd1h, bd1l, nullptr, x2, nullptr, 41, 20);
    // subm1a / subm1b: 3x3x3 SAME, output masked by m2
    conv_mma_kernel<1, true, true, false><<<dim3(128, 20), 512, SMEM_SUBM>>>(
        x2, b1ah, b1al, m2, x3, nullptr, 20, 20);
    conv_mma_kernel<1, true, true, false><<<dim3(128, 20), 512, SMEM_SUBM>>>(
        x3, b1bh, b1bl, m2, x1, nullptr, 20, 20);
    // down2 -> fp32 NCDHW output
    conv_mma_kernel<1, false, false, true><<<dim3(128, 9), 512, SMEM_DOWN>>>(
        x1, bd2h, bd2l, nullptr, nullptr, out, 20, 9);
}

// round 9
// speedup vs baseline: 1.5659x; 1.2374x over previous
#include <cuda_runtime.h>
#include <cuda_fp16.h>
#include <cstdint>

typedef unsigned int u32;
typedef unsigned long long u64;

#define HW 16384  // 128*128

// ============================================================================
// Static device scratch — activations single fp16, channels-last [d][h][w][ci]
// ============================================================================
__device__ __align__(16) __half g_x0[41 * HW * 128];
__device__ __align__(16) __half g_x1[41 * HW * 64];
__device__ __align__(16) __half g_x2[20 * HW * 64];
__device__ __align__(16) __half g_x3[20 * HW * 64];
__device__ float g_m0[41 * HW];
__device__ float g_m2[20 * HW];
// Weights: per-chunk [64 co][64 ci] fp16, PRE-SWIZZLED (SW128 XOR), hi/lo
__device__ __align__(16) __half g_B0h[54 * 4096], g_B0l[54 * 4096];
__device__ __align__(16) __half g_B1ah[27 * 4096], g_B1al[27 * 4096];
__device__ __align__(16) __half g_B1bh[27 * 4096], g_B1bl[27 * 4096];
__device__ __align__(16) __half g_Bd1h[3 * 4096], g_Bd1l[3 * 4096];
__device__ __align__(16) __half g_Bd2h[3 * 4096], g_Bd2l[3 * 4096];

// ============================================================================
// PTX helpers
// ============================================================================
__device__ __forceinline__ u32 smem_u32(const void* p) {
    u32 a;
    asm("{ .reg .u64 t; cvta.to.shared.u64 t, %1; cvt.u32.u64 %0, t; }"
        : "=r"(a) : "l"(p));
    return a;
}
__device__ __forceinline__ void cp_async16(u32 dst, const void* src, bool valid) {
    int sz = valid ? 16 : 0;
    asm volatile("cp.async.cg.shared.global [%0], [%1], 16, %2;"
                 :: "r"(dst), "l"(src), "r"(sz) : "memory");
}
__device__ __forceinline__ void cp_commit() {
    asm volatile("cp.async.commit_group;" ::: "memory");
}
template <int N>
__device__ __forceinline__ void cp_wait() {
    asm volatile("cp.async.wait_group %0;" :: "n"(N) : "memory");
}
#define LDMX4(r0, r1, r2, r3, addr) \
    asm volatile("ldmatrix.sync.aligned.m8n8.x4.shared.b16 {%0,%1,%2,%3}, [%4];" \
                 : "=r"(r0), "=r"(r1), "=r"(r2), "=r"(r3) : "r"(addr))

__device__ __forceinline__ void mma_f16(float* c, const u32* a, const u32* b) {
    asm volatile(
        "mma.sync.aligned.m16n8k16.row.col.f32.f16.f16.f32 "
        "{%0,%1,%2,%3}, {%4,%5,%6,%7}, {%8,%9}, {%0,%1,%2,%3};"
        : "+f"(c[0]), "+f"(c[1]), "+f"(c[2]), "+f"(c[3])
        : "r"(a[0]), "r"(a[1]), "r"(a[2]), "r"(a[3]), "r"(b[0]), "r"(b[1]));
}

__device__ __forceinline__ void split_f16(float v, __half& h, __half& l) {
    h = __float2half_rn(v);
    l = __float2half_rn(v - __half2float(h));
}
__device__ __forceinline__ int swidx(int co, int ci) {
    int ub = co * 128 + (ci >> 3) * 16;
    int sw = ub ^ ((ub >> 3) & 0x70);
    return (sw >> 1) + (ci & 7);
}
__device__ __forceinline__ u32 swz(u32 b) { return b ^ ((b >> 3) & 0x70); }

// ============================================================================
// Prep kernels
// ============================================================================
__global__ void prep_weights(const float* __restrict__ W0,
                             const float* __restrict__ Wd1,
                             const float* __restrict__ W1a,
                             const float* __restrict__ W1b,
                             const float* __restrict__ Wd2,
                             const float* __restrict__ mask)
{
    const int gid = blockIdx.x * blockDim.x + threadIdx.x;
    const int gs = gridDim.x * blockDim.x;

    for (int i = gid; i < 54 * 4096; i += gs) {
        int chunk = i >> 12, r = i & 4095, co = r >> 6, ci = r & 63;
        int cc = chunk & 1, tap = chunk >> 1;
        int kw = tap % 3, kh = (tap / 3) % 3, kd = tap / 9;
        float v = W0[(size_t)(co * 128 + cc * 64 + ci) * 27 + kd * 9 + kh * 3 + kw];
        __half h, l; split_f16(v, h, l);
        int dst = chunk * 4096 + swidx(co, ci);
        g_B0h[dst] = h; g_B0l[dst] = l;
    }
    for (int i = gid; i < 27 * 4096; i += gs) {
        int chunk = i >> 12, r = i & 4095, co = r >> 6, ci = r & 63;
        int kw = chunk % 3, kh = (chunk / 3) % 3, kd = chunk / 9;
        size_t src = (size_t)(co * 64 + ci) * 27 + kd * 9 + kh * 3 + kw;
        int dst = chunk * 4096 + swidx(co, ci);
        __half h, l;
        split_f16(W1a[src], h, l); g_B1ah[dst] = h; g_B1al[dst] = l;
        split_f16(W1b[src], h, l); g_B1bh[dst] = h; g_B1bl[dst] = l;
    }
    for (int i = gid; i < 3 * 4096; i += gs) {
        int chunk = i >> 12, r = i & 4095, co = r >> 6, ci = r & 63;
        size_t src = (size_t)(co * 64 + ci) * 3 + chunk;
        int dst = chunk * 4096 + swidx(co, ci);
        __half h, l;
        split_f16(Wd1[src], h, l); g_Bd1h[dst] = h; g_Bd1l[dst] = l;
        split_f16(Wd2[src], h, l); g_Bd2h[dst] = h; g_Bd2l[dst] = l;
    }
    for (int i = gid; i < 20 * HW; i += gs) {
        int dp = i >> 14, r = i & 16383;
        float a = mask[(size_t)(2 * dp) * HW + r];
        float b = mask[(size_t)(2 * dp + 1) * HW + r];
        float c = mask[(size_t)(2 * dp + 2) * HW + r];
        g_m2[i] = (fmaxf(a, fmaxf(b, c)) > 0.5f) ? 1.0f : 0.0f;
    }
}

__global__ void __launch_bounds__(256) conv0_pre(const float* __restrict__ feat,
                                                 const float* __restrict__ mask)
{
    const int h = blockIdx.x, d = blockIdx.y;
    const int tid = threadIdx.x;
    __shared__ float t[32][129];
    __shared__ float mrow[128];

    const size_t row0 = ((size_t)d * 128 + h) * 128;
    if (tid < 128) {
        float mv = mask[row0 + tid] > 0.5f ? 1.0f : 0.0f;
        mrow[tid] = mv;
        g_m0[row0 + tid] = mv;
    }
    __syncthreads();

    for (int cc = 0; cc < 4; ++cc) {
        #pragma unroll 1
        for (int i = tid; i < 32 * 128; i += 256) {
            int ci = i >> 7, w = i & 127;
            t[ci][w] = feat[((size_t)(cc * 32 + ci) * 41 + d) * HW + h * 128 + w];
        }
        __syncthreads();
        #pragma unroll 1
        for (int i = tid; i < 128 * 16; i += 256) {
            int w = i >> 4, p = i & 15;
            float mv = mrow[w];
            float v0 = t[p * 2][w] * mv;
            float v1 = t[p * 2 + 1][w] * mv;
            __half2 hv(__float2half_rn(v0), __float2half_rn(v1));
            size_t base = (row0 + w) * 128 + cc * 32;
            *(__half2*)(g_x0 + base + p * 2) = hv;
        }
        __syncthreads();
    }
}

// ============================================================================
// h-pair implicit-GEMM conv (mma.sync fp16, 2-term split Ah·(Bh+Bl)).
// CTA = TWO adjacent output h rows (h0 = 2*blockIdx.x, h1 = h0+1) at one dz:
// per stage (kd, kh_rel[, cc]) the SAME B tap serves both rows, with A tiles
// (din, hin0) and (din, hin0+1). B staging + B LDSM per output halved; each B
// fragment feeds 2 MMAs (A0, A1). 512 threads: warp_m = wid&7, warp_n = wid>>3.
// ============================================================================
template <int CC, bool K333, bool OMASK, bool FP32OUT>
__global__ void __launch_bounds__(512)
conv_mma_kernel(const __half* __restrict__ in,
                const __half* __restrict__ w_hi,
                const __half* __restrict__ w_lo,
                const float* __restrict__ omask,
                __half* __restrict__ out,
                float* __restrict__ out_f32,
                int Din, int Dout)
{
    constexpr int KW = K333 ? 3 : 1;
    constexpr int AROWS = K333 ? 130 : 128;
    constexpr int AE = AROWS * 8;                  // 16B segs per A tile
    constexpr int A_SPLIT = K333 ? 16896 : 16384;  // one A tile, padded
    constexpr int STAGE_A = 2 * A_SPLIT;
    constexpr int STAGE_B = KW * 16384;
    constexpr int STAGEB = STAGE_A + STAGE_B;

    extern __shared__ char smem[];
    const u32 smem_base = smem_u32(smem);
    const int tid = threadIdx.x;
    const int wid = tid >> 5;
    const int lane = tid & 31;
    const int h0 = blockIdx.x * 2;
    const int dz = blockIdx.y;
    const int CITOT = CC * 64;
    const int warp_m = wid & 7;
    const int warp_n = wid >> 3;

    __shared__ int s_din[18];
    __shared__ int s_aux[18];   // (hin0+1) | v0<<8 | v1<<9 | cc<<10 | wbase<<14
    __shared__ int s_n;
    __shared__ float s_mask[256];

    if (tid == 0) {
        int n = 0;
        if (K333) {
            for (int kd = 0; kd < 3; ++kd) {
                int din = dz + kd - 1;
                if (din < 0 || din >= Din) continue;
                for (int khr = 0; khr < 3; ++khr) {
                    int hin0 = h0 + khr - 1;            // -1..128
                    int v0 = (hin0 >= 0) ? 1 : 0;
                    int v1 = (hin0 + 1 <= 127) ? 1 : 0;
                    for (int cc = 0; cc < CC; ++cc) {
                        int wbase = ((kd * 3 + khr) * 3) * CC + cc;
                        s_din[n] = din;
                        s_aux[n] = (hin0 + 1) | (v0 << 8) | (v1 << 9) |
                                   (cc << 10) | (wbase << 14);
                        ++n;
                    }
                }
            }
        } else {
            for (int kd = 0; kd < 3; ++kd) {
                s_din[n] = 2 * dz + kd;
                s_aux[n] = (h0 + 1) | (1 << 8) | (1 << 9) | (kd << 14);
                ++n;
            }
        }
        s_n = n;
    }
    if (OMASK && tid < 256)
        s_mask[tid] = omask[((size_t)dz * 128 + h0 + (tid >> 7)) * 128 + (tid & 127)];
    __syncthreads();
    const int nch = s_n;

    // A ldmatrix addressing (stored row = m + kw for K333 halo; = m for down)
    u32 a_rowk[KW], a_sxk[KW];
    {
        int r = warp_m * 16 + (lane & 7) + ((lane >> 3) & 1) * 8;
        #pragma unroll
        for (int kw = 0; kw < KW; ++kw) {
            a_rowk[kw] = (u32)(r + kw) * 128;
            a_sxk[kw] = (u32)((r + kw) & 7) << 4;
        }
    }
    const u32 a_c = (u32)(lane >> 4) * 16;

    u32 b_row[2], b_sx[2];
    #pragma unroll
    for (int nh = 0; nh < 2; ++nh) {
        int rown = warp_n * 32 + nh * 16 + (lane & 7) + (lane >> 4) * 8;
        b_row[nh] = (u32)rown * 128;
        b_sx[nh] = (u32)(rown & 7) << 4;
    }
    const u32 b_c = (u32)((lane >> 3) & 1) * 16;

    // acc[tile][nt][q]: 2 h rows x (hh, hl) sets
    float acc_hh[2][4][4], acc_hl[2][4][4];
    #pragma unroll
    for (int tl = 0; tl < 2; ++tl)
        #pragma unroll
        for (int nt = 0; nt < 4; ++nt)
            #pragma unroll
            for (int q = 0; q < 4; ++q) {
                acc_hh[tl][nt][q] = 0.0f; acc_hl[tl][nt][q] = 0.0f;
            }

    // ---- staging ----
    auto stage = [&](int i, int buf) {
        const int din = s_din[i];
        const int aux = s_aux[i];
        const int hin0 = (aux & 255) - 1;
        const int v0 = (aux >> 8) & 1;
        const int v1 = (aux >> 9) & 1;
        const int cc = (aux >> 10) & 15;
        const int wb = aux >> 14;
        const u32 base = smem_base + (u32)buf * STAGEB;
        #pragma unroll 1
        for (int t = tid; t < 2 * AE; t += 512) {
            int tl = (t >= AE) ? 1 : 0;
            int u = t - tl * AE;
            int row = u >> 3, seg = u & 7;
            int win = K333 ? row - 1 : row;
            bool valid = (tl ? v1 : v0) && (!K333 || (unsigned)win < 128u);
            int hin = hin0 + tl;
            const char* src = (const char*)(in +
                (((size_t)din * 128 + (valid ? hin : 0)) * 128 +
                 (valid ? win : 0)) * CITOT + cc * 64) + seg * 16;
            cp_async16(base + tl * A_SPLIT + swz(row * 128 + seg * 16), src, valid);
        }
        #pragma unroll 1
        for (int t = tid; t < KW * 1024; t += 512) {
            int tile = t >> 9, idx = t & 511;
            int kw = tile >> 1, sp2 = tile & 1;
            const char* src = (const char*)((sp2 ? w_lo : w_hi) +
                (size_t)(wb + kw * CC) * 4096) + idx * 16;
            cp_async16(base + STAGE_A + kw * 16384 + sp2 * 8192 + idx * 16, src, true);
        }
        cp_commit();
    };

    stage(0, 0);
    for (int i = 0; i < nch; ++i) {
        const int buf = i & 1;
        if (i + 1 < nch) { stage(i + 1, buf ^ 1); cp_wait<1>(); }
        else             { cp_wait<0>(); }
        __syncthreads();

        const u32 ab = smem_base + (u32)buf * STAGEB;
        const u32 bb = ab + STAGE_A;

        #pragma unroll
        for (int kw = 0; kw < KW; ++kw) {
            const u32 bhi = bb + kw * 16384;
            const u32 blo = bhi + 8192;
            #pragma unroll
            for (int k16 = 0; k16 < 4; ++k16) {
                const u32 ko = k16 * 32;
                const u32 aoff = a_rowk[kw] + ((a_c + ko) ^ a_sxk[kw]);
                u32 A0[4], A1[4];
                LDMX4(A0[0], A0[1], A0[2], A0[3], ab + aoff);
                LDMX4(A1[0], A1[1], A1[2], A1[3], ab + A_SPLIT + aoff);
                u32 B0[4][2], B1[4][2];
                #pragma unroll
                for (int nh = 0; nh < 2; ++nh) {
                    const u32 boff = b_row[nh] + ((b_c + ko) ^ b_sx[nh]);
                    LDMX4(B0[2*nh][0], B0[2*nh][1], B0[2*nh+1][0], B0[2*nh+1][1],
                          bhi + boff);
                    LDMX4(B1[2*nh][0], B1[2*nh][1], B1[2*nh+1][0], B1[2*nh+1][1],
                          blo + boff);
                }
                #pragma unroll
                for (int nt = 0; nt < 4; ++nt) {
                    mma_f16(acc_hh[0][nt], A0, B0[nt]);
                    mma_f16(acc_hh[1][nt], A1, B0[nt]);
                    mma_f16(acc_hl[0][nt], A0, B1[nt]);
                    mma_f16(acc_hl[1][nt], A1, B1[nt]);
                }
            }
        }
        __syncthreads();
    }

    // ---- epilogue ----
    const int g = lane >> 2, tg = lane & 3;
    #pragma unroll
    for (int tl = 0; tl < 2; ++tl) {
        const int h = h0 + tl;
        #pragma unroll
        for (int half = 0; half < 2; ++half) {
            const int m = warp_m * 16 + g + half * 8;
            const float mv = OMASK ? s_mask[tl * 128 + m] : 1.0f;
            const size_t row = ((size_t)dz * 128 + h) * 128 + m;
            #pragma unroll
            for (int nt = 0; nt < 4; ++nt) {
                const int n0 = warp_n * 32 + nt * 8 + tg * 2;
                const int q0 = half * 2;
                float v0 = acc_hh[tl][nt][q0]   + acc_hl[tl][nt][q0];
                float v1 = acc_hh[tl][nt][q0+1] + acc_hl[tl][nt][q0+1];
                v0 = fmaxf(v0 * mv, 0.0f);
                v1 = fmaxf(v1 * mv, 0.0f);
                if (FP32OUT) {
                    out_f32[((size_t)n0 * Dout + dz) * HW + h * 128 + m] = v0;
                    out_f32[((size_t)(n0 + 1) * Dout + dz) * HW + h * 128 + m] = v1;
                } else {
                    __half2 hv(__float2half_rn(v0), __float2half_rn(v1));
                    *(u32*)(out + row * 64 + n0) = *(u32*)&hv;
                }
            }
        }
    }
}

#define SMEM_SUBM (2 * (2 * 16896 + 3 * 16384))   // 165888
#define SMEM_DOWN (2 * (2 * 16384 + 1 * 16384))   // 98304

// ============================================================================
extern "C" void kernel_launch(void* const* d_in, const int* in_sizes, int n_in,
                              void* d_out, int out_size)
{
    const float* feat = (const float*)d_in[0];
    const float* mask = (const float*)d_in[1];
    const float* W0   = (const float*)d_in[2];
    const float* Wd1  = (const float*)d_in[3];
    const float* W1a  = (const float*)d_in[4];
    const float* W1b  = (const float*)d_in[5];
    const float* Wd2  = (const float*)d_in[6];
    float* out = (float*)d_out;

    void* p;
    #define SYM(v, s) cudaGetSymbolAddress(&p, s); auto* v = (decltype(&s[0]))p;
    SYM(x0, g_x0) SYM(x1, g_x1) SYM(x2, g_x2) SYM(x3, g_x3)
    SYM(m0, g_m0) SYM(m2, g_m2)
    SYM(b0h, g_B0h)   SYM(b0l, g_B0l)
    SYM(b1ah, g_B1ah) SYM(b1al, g_B1al)
    SYM(b1bh, g_B1bh) SYM(b1bl, g_B1bl)
    SYM(bd1h, g_Bd1h) SYM(bd1l, g_Bd1l)
    SYM(bd2h, g_Bd2h) SYM(bd2l, g_Bd2l)
    #undef SYM

    cudaFuncSetAttribute(conv_mma_kernel<2, true, true, false>,
                         cudaFuncAttributeMaxDynamicSharedMemorySize, SMEM_SUBM);
    cudaFuncSetAttribute(conv_mma_kernel<1, true, true, false>,
                         cudaFuncAttributeMaxDynamicSharedMemorySize, SMEM_SUBM);
    cudaFuncSetAttribute(conv_mma_kernel<1, false, false, false>,
                         cudaFuncAttributeMaxDynamicSharedMemorySize, SMEM_DOWN);
    cudaFuncSetAttribute(conv_mma_kernel<1, false, false, true>,
                         cudaFuncAttributeMaxDynamicSharedMemorySize, SMEM_DOWN);

    prep_weights<<<264, 256>>>(W0, Wd1, W1a, W1b, Wd2, mask);
    conv0_pre<<<dim3(128, 41), 256>>>(feat, mask);

    // conv0: 128->64, 3x3x3 SAME, output masked by m0 (input pre-masked)
    conv_mma_kernel<2, true, true, false><<<dim3(64, 41), 512, SMEM_SUBM>>>(
        x0, b0h, b0l, m0, x1, nullptr, 41, 41);
    // down1: (3,1,1)/stride(2,1,1), relu
    conv_mma_kernel<1, false, false, false><<<dim3(64, 20), 512, SMEM_DOWN>>>(
        x1, bd1h, bd1l, nullptr, x2, nullptr, 41, 20);
    // subm1a / subm1b: 3x3x3 SAME, output masked by m2
    conv_mma_kernel<1, true, true, false><<<dim3(64, 20), 512, SMEM_SUBM>>>(
        x2, b1ah, b1al, m2, x3, nullptr, 20, 20);
    conv_mma_kernel<1, true, true, false><<<dim3(64, 20), 512, SMEM_SUBM>>>(
        x3, b1bh, b1bl, m2, x1, nullptr, 20, 20);
    // down2 -> fp32 NCDHW output
    conv_mma_kernel<1, false, false, true><<<dim3(64, 9), 512, SMEM_DOWN>>>(
        x1, bd2h, bd2l, nullptr, nullptr, out, 20, 9);
}

// round 10
// speedup vs baseline: 1.5789x; 1.0083x over previous
#include <cuda_runtime.h>
#include <cuda_fp16.h>
#include <cstdint>

typedef unsigned int u32;
typedef unsigned long long u64;

#define HW 16384  // 128*128

// ============================================================================
// Static device scratch — activations single fp16, channels-last [d][h][w][ci]
// ============================================================================
__device__ __align__(16) __half g_x0[41 * HW * 128];
__device__ __align__(16) __half g_x1[41 * HW * 64];
__device__ __align__(16) __half g_x2[20 * HW * 64];
__device__ __align__(16) __half g_x3[20 * HW * 64];
__device__ float g_m0[41 * HW];
__device__ float g_m2[20 * HW];
// Weights: per-chunk [64 co][64 ci] fp16, PRE-SWIZZLED (SW128 XOR), hi/lo
__device__ __align__(16) __half g_B0h[54 * 4096], g_B0l[54 * 4096];
__device__ __align__(16) __half g_B1ah[27 * 4096], g_B1al[27 * 4096];
__device__ __align__(16) __half g_B1bh[27 * 4096], g_B1bl[27 * 4096];
__device__ __align__(16) __half g_Bd1h[3 * 4096], g_Bd1l[3 * 4096];
__device__ __align__(16) __half g_Bd2h[3 * 4096], g_Bd2l[3 * 4096];

// ============================================================================
// PTX helpers
// ============================================================================
__device__ __forceinline__ u32 smem_u32(const void* p) {
    u32 a;
    asm("{ .reg .u64 t; cvta.to.shared.u64 t, %1; cvt.u32.u64 %0, t; }"
        : "=r"(a) : "l"(p));
    return a;
}
__device__ __forceinline__ void cp_async16(u32 dst, const void* src, bool valid) {
    int sz = valid ? 16 : 0;
    asm volatile("cp.async.cg.shared.global [%0], [%1], 16, %2;"
                 :: "r"(dst), "l"(src), "r"(sz) : "memory");
}
__device__ __forceinline__ void cp_commit() {
    asm volatile("cp.async.commit_group;" ::: "memory");
}
template <int N>
__device__ __forceinline__ void cp_wait() {
    asm volatile("cp.async.wait_group %0;" :: "n"(N) : "memory");
}
#define LDMX4(r0, r1, r2, r3, addr) \
    asm volatile("ldmatrix.sync.aligned.m8n8.x4.shared.b16 {%0,%1,%2,%3}, [%4];" \
                 : "=r"(r0), "=r"(r1), "=r"(r2), "=r"(r3) : "r"(addr))

// main term: f32 accumulate
__device__ __forceinline__ void mma_f16(float* c, const u32* a, const u32* b) {
    asm volatile(
        "mma.sync.aligned.m16n8k16.row.col.f32.f16.f16.f32 "
        "{%0,%1,%2,%3}, {%4,%5,%6,%7}, {%8,%9}, {%0,%1,%2,%3};"
        : "+f"(c[0]), "+f"(c[1]), "+f"(c[2]), "+f"(c[3])
        : "r"(a[0]), "r"(a[1]), "r"(a[2]), "r"(a[3]), "r"(b[0]), "r"(b[1]));
}
// correction term (Ah*Bl ~ 2^-11 of output): f16 accumulate — possibly 2x rate
__device__ __forceinline__ void mma_f16_h(u32* c, const u32* a, const u32* b) {
    asm volatile(
        "mma.sync.aligned.m16n8k16.row.col.f16.f16.f16.f16 "
        "{%0,%1}, {%2,%3,%4,%5}, {%6,%7}, {%0,%1};"
        : "+r"(c[0]), "+r"(c[1])
        : "r"(a[0]), "r"(a[1]), "r"(a[2]), "r"(a[3]), "r"(b[0]), "r"(b[1]));
}

__device__ __forceinline__ void split_f16(float v, __half& h, __half& l) {
    h = __float2half_rn(v);
    l = __float2half_rn(v - __half2float(h));
}
__device__ __forceinline__ int swidx(int co, int ci) {
    int ub = co * 128 + (ci >> 3) * 16;
    int sw = ub ^ ((ub >> 3) & 0x70);
    return (sw >> 1) + (ci & 7);
}
__device__ __forceinline__ u32 swz(u32 b) { return b ^ ((b >> 3) & 0x70); }

// ============================================================================
// Prep kernels
// ============================================================================
__global__ void prep_weights(const float* __restrict__ W0,
                             const float* __restrict__ Wd1,
                             const float* __restrict__ W1a,
                             const float* __restrict__ W1b,
                             const float* __restrict__ Wd2,
                             const float* __restrict__ mask)
{
    const int gid = blockIdx.x * blockDim.x + threadIdx.x;
    const int gs = gridDim.x * blockDim.x;

    for (int i = gid; i < 54 * 4096; i += gs) {
        int chunk = i >> 12, r = i & 4095, co = r >> 6, ci = r & 63;
        int cc = chunk & 1, tap = chunk >> 1;
        int kw = tap % 3, kh = (tap / 3) % 3, kd = tap / 9;
        float v = W0[(size_t)(co * 128 + cc * 64 + ci) * 27 + kd * 9 + kh * 3 + kw];
        __half h, l; split_f16(v, h, l);
        int dst = chunk * 4096 + swidx(co, ci);
        g_B0h[dst] = h; g_B0l[dst] = l;
    }
    for (int i = gid; i < 27 * 4096; i += gs) {
        int chunk = i >> 12, r = i & 4095, co = r >> 6, ci = r & 63;
        int kw = chunk % 3, kh = (chunk / 3) % 3, kd = chunk / 9;
        size_t src = (size_t)(co * 64 + ci) * 27 + kd * 9 + kh * 3 + kw;
        int dst = chunk * 4096 + swidx(co, ci);
        __half h, l;
        split_f16(W1a[src], h, l); g_B1ah[dst] = h; g_B1al[dst] = l;
        split_f16(W1b[src], h, l); g_B1bh[dst] = h; g_B1bl[dst] = l;
    }
    for (int i = gid; i < 3 * 4096; i += gs) {
        int chunk = i >> 12, r = i & 4095, co = r >> 6, ci = r & 63;
        size_t src = (size_t)(co * 64 + ci) * 3 + chunk;
        int dst = chunk * 4096 + swidx(co, ci);
        __half h, l;
        split_f16(Wd1[src], h, l); g_Bd1h[dst] = h; g_Bd1l[dst] = l;
        split_f16(Wd2[src], h, l); g_Bd2h[dst] = h; g_Bd2l[dst] = l;
    }
    for (int i = gid; i < 20 * HW; i += gs) {
        int dp = i >> 14, r = i & 16383;
        float a = mask[(size_t)(2 * dp) * HW + r];
        float b = mask[(size_t)(2 * dp + 1) * HW + r];
        float c = mask[(size_t)(2 * dp + 2) * HW + r];
        g_m2[i] = (fmaxf(a, fmaxf(b, c)) > 0.5f) ? 1.0f : 0.0f;
    }
}

__global__ void __launch_bounds__(256) conv0_pre(const float* __restrict__ feat,
                                                 const float* __restrict__ mask)
{
    const int h = blockIdx.x, d = blockIdx.y;
    const int tid = threadIdx.x;
    __shared__ float t[32][129];
    __shared__ float mrow[128];

    const size_t row0 = ((size_t)d * 128 + h) * 128;
    if (tid < 128) {
        float mv = mask[row0 + tid] > 0.5f ? 1.0f : 0.0f;
        mrow[tid] = mv;
        g_m0[row0 + tid] = mv;
    }
    __syncthreads();

    for (int cc = 0; cc < 4; ++cc) {
        #pragma unroll 1
        for (int i = tid; i < 32 * 128; i += 256) {
            int ci = i >> 7, w = i & 127;
            t[ci][w] = feat[((size_t)(cc * 32 + ci) * 41 + d) * HW + h * 128 + w];
        }
        __syncthreads();
        #pragma unroll 1
        for (int i = tid; i < 128 * 16; i += 256) {
            int w = i >> 4, p = i & 15;
            float mv = mrow[w];
            float v0 = t[p * 2][w] * mv;
            float v1 = t[p * 2 + 1][w] * mv;
            __half2 hv(__float2half_rn(v0), __float2half_rn(v1));
            size_t base = (row0 + w) * 128 + cc * 32;
            *(__half2*)(g_x0 + base + p * 2) = hv;
        }
        __syncthreads();
    }
}

// ============================================================================
// h-pair implicit-GEMM conv (mma.sync fp16, 2-term split Ah·(Bh+Bl)).
// hh term: f32 accum; hl term: f16 accum (error ~2^-22 overall, possibly 2x rate).
// CTA = TWO adjacent output h rows; same B tap serves both rows.
// 512 threads: warp_m = wid&7 (m16), warp_n = wid>>3 (n32).
// ============================================================================
template <int CC, bool K333, bool OMASK, bool FP32OUT>
__global__ void __launch_bounds__(512)
conv_mma_kernel(const __half* __restrict__ in,
                const __half* __restrict__ w_hi,
                const __half* __restrict__ w_lo,
                const float* __restrict__ omask,
                __half* __restrict__ out,
                float* __restrict__ out_f32,
                int Din, int Dout)
{
    constexpr int KW = K333 ? 3 : 1;
    constexpr int AROWS = K333 ? 130 : 128;
    constexpr int AE = AROWS * 8;                  // 16B segs per A tile
    constexpr int A_SPLIT = K333 ? 16896 : 16384;  // one A tile, padded
    constexpr int STAGE_A = 2 * A_SPLIT;
    constexpr int STAGE_B = KW * 16384;
    constexpr int STAGEB = STAGE_A + STAGE_B;

    extern __shared__ char smem[];
    const u32 smem_base = smem_u32(smem);
    const int tid = threadIdx.x;
    const int wid = tid >> 5;
    const int lane = tid & 31;
    const int h0 = blockIdx.x * 2;
    const int dz = blockIdx.y;
    const int CITOT = CC * 64;
    const int warp_m = wid & 7;
    const int warp_n = wid >> 3;

    __shared__ int s_din[18];
    __shared__ int s_aux[18];   // (hin0+1) | v0<<8 | v1<<9 | cc<<10 | wbase<<14
    __shared__ int s_n;
    __shared__ float s_mask[256];

    if (tid == 0) {
        int n = 0;
        if (K333) {
            for (int kd = 0; kd < 3; ++kd) {
                int din = dz + kd - 1;
                if (din < 0 || din >= Din) continue;
                for (int khr = 0; khr < 3; ++khr) {
                    int hin0 = h0 + khr - 1;            // -1..128
                    int v0 = (hin0 >= 0) ? 1 : 0;
                    int v1 = (hin0 + 1 <= 127) ? 1 : 0;
                    for (int cc = 0; cc < CC; ++cc) {
                        int wbase = ((kd * 3 + khr) * 3) * CC + cc;
                        s_din[n] = din;
                        s_aux[n] = (hin0 + 1) | (v0 << 8) | (v1 << 9) |
                                   (cc << 10) | (wbase << 14);
                        ++n;
                    }
                }
            }
        } else {
            for (int kd = 0; kd < 3; ++kd) {
                s_din[n] = 2 * dz + kd;
                s_aux[n] = (h0 + 1) | (1 << 8) | (1 << 9) | (kd << 14);
                ++n;
            }
        }
        s_n = n;
    }
    if (OMASK && tid < 256)
        s_mask[tid] = omask[((size_t)dz * 128 + h0 + (tid >> 7)) * 128 + (tid & 127)];
    __syncthreads();
    const int nch = s_n;

    // A ldmatrix addressing (stored row = m + kw for K333 halo; = m for down)
    u32 a_rowk[KW], a_sxk[KW];
    {
        int r = warp_m * 16 + (lane & 7) + ((lane >> 3) & 1) * 8;
        #pragma unroll
        for (int kw = 0; kw < KW; ++kw) {
            a_rowk[kw] = (u32)(r + kw) * 128;
            a_sxk[kw] = (u32)((r + kw) & 7) << 4;
        }
    }
    const u32 a_c = (u32)(lane >> 4) * 16;

    u32 b_row[2], b_sx[2];
    #pragma unroll
    for (int nh = 0; nh < 2; ++nh) {
        int rown = warp_n * 32 + nh * 16 + (lane & 7) + (lane >> 4) * 8;
        b_row[nh] = (u32)rown * 128;
        b_sx[nh] = (u32)(rown & 7) << 4;
    }
    const u32 b_c = (u32)((lane >> 3) & 1) * 16;

    // hh: f32 accum; hl: f16 accum (packed half2 x2)
    float acc_hh[2][4][4];
    u32 acc_hl[2][4][2];
    #pragma unroll
    for (int tl = 0; tl < 2; ++tl)
        #pragma unroll
        for (int nt = 0; nt < 4; ++nt) {
            #pragma unroll
            for (int q = 0; q < 4; ++q) acc_hh[tl][nt][q] = 0.0f;
            acc_hl[tl][nt][0] = 0u; acc_hl[tl][nt][1] = 0u;
        }

    // ---- staging ----
    auto stage = [&](int i, int buf) {
        const int din = s_din[i];
        const int aux = s_aux[i];
        const int hin0 = (aux & 255) - 1;
        const int v0 = (aux >> 8) & 1;
        const int v1 = (aux >> 9) & 1;
        const int cc = (aux >> 10) & 15;
        const int wb = aux >> 14;
        const u32 base = smem_base + (u32)buf * STAGEB;
        #pragma unroll 1
        for (int t = tid; t < 2 * AE; t += 512) {
            int tl = (t >= AE) ? 1 : 0;
            int u = t - tl * AE;
            int row = u >> 3, seg = u & 7;
            int win = K333 ? row - 1 : row;
            bool valid = (tl ? v1 : v0) && (!K333 || (unsigned)win < 128u);
            int hin = hin0 + tl;
            const char* src = (const char*)(in +
                (((size_t)din * 128 + (valid ? hin : 0)) * 128 +
                 (valid ? win : 0)) * CITOT + cc * 64) + seg * 16;
            cp_async16(base + tl * A_SPLIT + swz(row * 128 + seg * 16), src, valid);
        }
        #pragma unroll 1
        for (int t = tid; t < KW * 1024; t += 512) {
            int tile = t >> 9, idx = t & 511;
            int kw = tile >> 1, sp2 = tile & 1;
            const char* src = (const char*)((sp2 ? w_lo : w_hi) +
                (size_t)(wb + kw * CC) * 4096) + idx * 16;
            cp_async16(base + STAGE_A + kw * 16384 + sp2 * 8192 + idx * 16, src, true);
        }
        cp_commit();
    };

    stage(0, 0);
    for (int i = 0; i < nch; ++i) {
        const int buf = i & 1;
        if (i + 1 < nch) { stage(i + 1, buf ^ 1); cp_wait<1>(); }
        else             { cp_wait<0>(); }
        __syncthreads();

        const u32 ab = smem_base + (u32)buf * STAGEB;
        const u32 bb = ab + STAGE_A;

        #pragma unroll
        for (int kw = 0; kw < KW; ++kw) {
            const u32 bhi = bb + kw * 16384;
            const u32 blo = bhi + 8192;
            #pragma unroll
            for (int k16 = 0; k16 < 4; ++k16) {
                const u32 ko = k16 * 32;
                const u32 aoff = a_rowk[kw] + ((a_c + ko) ^ a_sxk[kw]);
                u32 A0[4], A1[4];
                LDMX4(A0[0], A0[1], A0[2], A0[3], ab + aoff);
                LDMX4(A1[0], A1[1], A1[2], A1[3], ab + A_SPLIT + aoff);
                u32 B0[4][2], B1[4][2];
                #pragma unroll
                for (int nh = 0; nh < 2; ++nh) {
                    const u32 boff = b_row[nh] + ((b_c + ko) ^ b_sx[nh]);
                    LDMX4(B0[2*nh][0], B0[2*nh][1], B0[2*nh+1][0], B0[2*nh+1][1],
                          bhi + boff);
                    LDMX4(B1[2*nh][0], B1[2*nh][1], B1[2*nh+1][0], B1[2*nh+1][1],
                          blo + boff);
                }
                #pragma unroll
                for (int nt = 0; nt < 4; ++nt) {
                    mma_f16(acc_hh[0][nt], A0, B0[nt]);
                    mma_f16(acc_hh[1][nt], A1, B0[nt]);
                    mma_f16_h(acc_hl[0][nt], A0, B1[nt]);
                    mma_f16_h(acc_hl[1][nt], A1, B1[nt]);
                }
            }
        }
        __syncthreads();
    }

    // ---- epilogue ----
    const int g = lane >> 2, tg = lane & 3;
    #pragma unroll
    for (int tl = 0; tl < 2; ++tl) {
        const int h = h0 + tl;
        #pragma unroll
        for (int half = 0; half < 2; ++half) {
            const int m = warp_m * 16 + g + half * 8;
            const float mv = OMASK ? s_mask[tl * 128 + m] : 1.0f;
            const size_t row = ((size_t)dz * 128 + h) * 128 + m;
            #pragma unroll
            for (int nt = 0; nt < 4; ++nt) {
                const int n0 = warp_n * 32 + nt * 8 + tg * 2;
                const int q0 = half * 2;
                __half2 hl = *(__half2*)&acc_hl[tl][nt][half];
                float v0 = acc_hh[tl][nt][q0]   + __low2float(hl);
                float v1 = acc_hh[tl][nt][q0+1] + __high2float(hl);
                v0 = fmaxf(v0 * mv, 0.0f);
                v1 = fmaxf(v1 * mv, 0.0f);
                if (FP32OUT) {
                    out_f32[((size_t)n0 * Dout + dz) * HW + h * 128 + m] = v0;
                    out_f32[((size_t)(n0 + 1) * Dout + dz) * HW + h * 128 + m] = v1;
                } else {
                    __half2 hv(__float2half_rn(v0), __float2half_rn(v1));
                    *(u32*)(out + row * 64 + n0) = *(u32*)&hv;
                }
            }
        }
    }
}

#define SMEM_SUBM (2 * (2 * 16896 + 3 * 16384))   // 165888
#define SMEM_DOWN (2 * (2 * 16384 + 1 * 16384))   // 98304

// ============================================================================
extern "C" void kernel_launch(void* const* d_in, const int* in_sizes, int n_in,
                              void* d_out, int out_size)
{
    const float* feat = (const float*)d_in[0];
    const float* mask = (const float*)d_in[1];
    const float* W0   = (const float*)d_in[2];
    const float* Wd1  = (const float*)d_in[3];
    const float* W1a  = (const float*)d_in[4];
    const float* W1b  = (const float*)d_in[5];
    const float* Wd2  = (const float*)d_in[6];
    float* out = (float*)d_out;

    void* p;
    #define SYM(v, s) cudaGetSymbolAddress(&p, s); auto* v = (decltype(&s[0]))p;
    SYM(x0, g_x0) SYM(x1, g_x1) SYM(x2, g_x2) SYM(x3, g_x3)
    SYM(m0, g_m0) SYM(m2, g_m2)
    SYM(b0h, g_B0h)   SYM(b0l, g_B0l)
    SYM(b1ah, g_B1ah) SYM(b1al, g_B1al)
    SYM(b1bh, g_B1bh) SYM(b1bl, g_B1bl)
    SYM(bd1h, g_Bd1h) SYM(bd1l, g_Bd1l)
    SYM(bd2h, g_Bd2h) SYM(bd2l, g_Bd2l)
    #undef SYM

    cudaFuncSetAttribute(conv_mma_kernel<2, true, true, false>,
                         cudaFuncAttributeMaxDynamicSharedMemorySize, SMEM_SUBM);
    cudaFuncSetAttribute(conv_mma_kernel<1, true, true, false>,
                         cudaFuncAttributeMaxDynamicSharedMemorySize, SMEM_SUBM);
    cudaFuncSetAttribute(conv_mma_kernel<1, false, false, false>,
                         cudaFuncAttributeMaxDynamicSharedMemorySize, SMEM_DOWN);
    cudaFuncSetAttribute(conv_mma_kernel<1, false, false, true>,
                         cudaFuncAttributeMaxDynamicSharedMemorySize, SMEM_DOWN);

    prep_weights<<<264, 256>>>(W0, Wd1, W1a, W1b, Wd2, mask);
    conv0_pre<<<dim3(128, 41), 256>>>(feat, mask);

    // conv0: 128->64, 3x3x3 SAME, output masked by m0 (input pre-masked)
    conv_mma_kernel<2, true, true, false><<<dim3(64, 41), 512, SMEM_SUBM>>>(
        x0, b0h, b0l, m0, x1, nullptr, 41, 41);
    // down1: (3,1,1)/stride(2,1,1), relu
    conv_mma_kernel<1, false, false, false><<<dim3(64, 20), 512, SMEM_DOWN>>>(
        x1, bd1h, bd1l, nullptr, x2, nullptr, 41, 20);
    // subm1a / subm1b: 3x3x3 SAME, output masked by m2
    conv_mma_kernel<1, true, true, false><<<dim3(64, 20), 512, SMEM_SUBM>>>(
        x2, b1ah, b1al, m2, x3, nullptr, 20, 20);
    conv_mma_kernel<1, true, true, false><<<dim3(64, 20), 512, SMEM_SUBM>>>(
        x3, b1bh, b1bl, m2, x1, nullptr, 20, 20);
    // down2 -> fp32 NCDHW output
    conv_mma_kernel<1, false, false, true><<<dim3(64, 9), 512, SMEM_DOWN>>>(
        x1, bd2h, bd2l, nullptr, nullptr, out, 20, 9);
}

// round 11
// speedup vs baseline: 2.4900x; 1.5770x over previous
#include <cuda_runtime.h>
#include <cuda_fp16.h>
#include <cstdint>

typedef unsigned int u32;
typedef unsigned long long u64;

#define HW 16384  // 128*128

// ============================================================================
// Static device scratch — activations single fp16, channels-last [d][h][w][ci]
// ============================================================================
__device__ __align__(16) __half g_x0[41 * HW * 128];
__device__ __align__(16) __half g_x1[41 * HW * 64];
__device__ __align__(16) __half g_x2[20 * HW * 64];
__device__ __align__(16) __half g_x3[20 * HW * 64];
__device__ float g_m0[41 * HW];
__device__ float g_m2[20 * HW];
// Weights: per-chunk [64 co][64 ci] fp16, PRE-SWIZZLED (SW128 XOR), single term
__device__ __align__(16) __half g_B0[54 * 4096];
__device__ __align__(16) __half g_B1a[27 * 4096];
__device__ __align__(16) __half g_B1b[27 * 4096];
__device__ __align__(16) __half g_Bd1[3 * 4096];
__device__ __align__(16) __half g_Bd2[3 * 4096];

// ============================================================================
// PTX helpers
// ============================================================================
__device__ __forceinline__ u32 smem_u32(const void* p) {
    u32 a;
    asm("{ .reg .u64 t; cvta.to.shared.u64 t, %1; cvt.u32.u64 %0, t; }"
        : "=r"(a) : "l"(p));
    return a;
}
__device__ __forceinline__ void cp_async16(u32 dst, const void* src, bool valid) {
    int sz = valid ? 16 : 0;
    asm volatile("cp.async.cg.shared.global [%0], [%1], 16, %2;"
                 :: "r"(dst), "l"(src), "r"(sz) : "memory");
}
__device__ __forceinline__ void cp_commit() {
    asm volatile("cp.async.commit_group;" ::: "memory");
}
template <int N>
__device__ __forceinline__ void cp_wait() {
    asm volatile("cp.async.wait_group %0;" :: "n"(N) : "memory");
}
#define LDMX4(r0, r1, r2, r3, addr) \
    asm volatile("ldmatrix.sync.aligned.m8n8.x4.shared.b16 {%0,%1,%2,%3}, [%4];" \
                 : "=r"(r0), "=r"(r1), "=r"(r2), "=r"(r3) : "r"(addr))

__device__ __forceinline__ void mma_f16(float* c, const u32* a, const u32* b) {
    asm volatile(
        "mma.sync.aligned.m16n8k16.row.col.f32.f16.f16.f32 "
        "{%0,%1,%2,%3}, {%4,%5,%6,%7}, {%8,%9}, {%0,%1,%2,%3};"
        : "+f"(c[0]), "+f"(c[1]), "+f"(c[2]), "+f"(c[3])
        : "r"(a[0]), "r"(a[1]), "r"(a[2]), "r"(a[3]), "r"(b[0]), "r"(b[1]));
}

__device__ __forceinline__ int swidx(int co, int ci) {
    int ub = co * 128 + (ci >> 3) * 16;
    int sw = ub ^ ((ub >> 3) & 0x70);
    return (sw >> 1) + (ci & 7);
}
__device__ __forceinline__ u32 swz(u32 b) { return b ^ ((b >> 3) & 0x70); }

// ============================================================================
// Prep kernels
// ============================================================================
__global__ void prep_weights(const float* __restrict__ W0,
                             const float* __restrict__ Wd1,
                             const float* __restrict__ W1a,
                             const float* __restrict__ W1b,
                             const float* __restrict__ Wd2,
                             const float* __restrict__ mask)
{
    const int gid = blockIdx.x * blockDim.x + threadIdx.x;
    const int gs = gridDim.x * blockDim.x;

    for (int i = gid; i < 54 * 4096; i += gs) {
        int chunk = i >> 12, r = i & 4095, co = r >> 6, ci = r & 63;
        int cc = chunk & 1, tap = chunk >> 1;
        int kw = tap % 3, kh = (tap / 3) % 3, kd = tap / 9;
        float v = W0[(size_t)(co * 128 + cc * 64 + ci) * 27 + kd * 9 + kh * 3 + kw];
        g_B0[chunk * 4096 + swidx(co, ci)] = __float2half_rn(v);
    }
    for (int i = gid; i < 27 * 4096; i += gs) {
        int chunk = i >> 12, r = i & 4095, co = r >> 6, ci = r & 63;
        int kw = chunk % 3, kh = (chunk / 3) % 3, kd = chunk / 9;
        size_t src = (size_t)(co * 64 + ci) * 27 + kd * 9 + kh * 3 + kw;
        int dst = chunk * 4096 + swidx(co, ci);
        g_B1a[dst] = __float2half_rn(W1a[src]);
        g_B1b[dst] = __float2half_rn(W1b[src]);
    }
    for (int i = gid; i < 3 * 4096; i += gs) {
        int chunk = i >> 12, r = i & 4095, co = r >> 6, ci = r & 63;
        size_t src = (size_t)(co * 64 + ci) * 3 + chunk;
        int dst = chunk * 4096 + swidx(co, ci);
        g_Bd1[dst] = __float2half_rn(Wd1[src]);
        g_Bd2[dst] = __float2half_rn(Wd2[src]);
    }
    for (int i = gid; i < 20 * HW; i += gs) {
        int dp = i >> 14, r = i & 16383;
        float a = mask[(size_t)(2 * dp) * HW + r];
        float b = mask[(size_t)(2 * dp + 1) * HW + r];
        float c = mask[(size_t)(2 * dp + 2) * HW + r];
        g_m2[i] = (fmaxf(a, fmaxf(b, c)) > 0.5f) ? 1.0f : 0.0f;
    }
}

__global__ void __launch_bounds__(256) conv0_pre(const float* __restrict__ feat,
                                                 const float* __restrict__ mask)
{
    const int h = blockIdx.x, d = blockIdx.y;
    const int tid = threadIdx.x;
    __shared__ float t[32][129];
    __shared__ float mrow[128];

    const size_t row0 = ((size_t)d * 128 + h) * 128;
    if (tid < 128) {
        float mv = mask[row0 + tid] > 0.5f ? 1.0f : 0.0f;
        mrow[tid] = mv;
        g_m0[row0 + tid] = mv;
    }
    __syncthreads();

    for (int cc = 0; cc < 4; ++cc) {
        #pragma unroll 1
        for (int i = tid; i < 32 * 128; i += 256) {
            int ci = i >> 7, w = i & 127;
            t[ci][w] = feat[((size_t)(cc * 32 + ci) * 41 + d) * HW + h * 128 + w];
        }
        __syncthreads();
        #pragma unroll 1
        for (int i = tid; i < 128 * 16; i += 256) {
            int w = i >> 4, p = i & 15;
            float mv = mrow[w];
            float v0 = t[p * 2][w] * mv;
            float v1 = t[p * 2 + 1][w] * mv;
            __half2 hv(__float2half_rn(v0), __float2half_rn(v1));
            size_t base = (row0 + w) * 128 + cc * 32;
            *(__half2*)(g_x0 + base + p * 2) = hv;
        }
        __syncthreads();
    }
}

// ============================================================================
// h-pair implicit-GEMM conv (mma.sync fp16, single-term: A·W, both fp16-rn).
// CTA = TWO adjacent output h rows; same B tap serves both rows.
// 512 threads: warp_m = wid&7 (m16), warp_n = wid>>3 (n32).
// ============================================================================
template <int CC, bool K333, bool OMASK, bool FP32OUT>
__global__ void __launch_bounds__(512)
conv_mma_kernel(const __half* __restrict__ in,
                const __half* __restrict__ wt,
                const float* __restrict__ omask,
                __half* __restrict__ out,
                float* __restrict__ out_f32,
                int Din, int Dout)
{
    constexpr int KW = K333 ? 3 : 1;
    constexpr int AROWS = K333 ? 130 : 128;
    constexpr int AE = AROWS * 8;                  // 16B segs per A tile
    constexpr int A_SPLIT = K333 ? 16896 : 16384;  // one A tile, padded
    constexpr int STAGE_A = 2 * A_SPLIT;
    constexpr int STAGE_B = KW * 8192;
    constexpr int STAGEB = STAGE_A + STAGE_B;

    extern __shared__ char smem[];
    const u32 smem_base = smem_u32(smem);
    const int tid = threadIdx.x;
    const int wid = tid >> 5;
    const int lane = tid & 31;
    const int h0 = blockIdx.x * 2;
    const int dz = blockIdx.y;
    const int CITOT = CC * 64;
    const int warp_m = wid & 7;
    const int warp_n = wid >> 3;

    __shared__ int s_din[18];
    __shared__ int s_aux[18];   // (hin0+1) | v0<<8 | v1<<9 | cc<<10 | wbase<<14
    __shared__ int s_n;
    __shared__ float s_mask[256];

    if (tid == 0) {
        int n = 0;
        if (K333) {
            for (int kd = 0; kd < 3; ++kd) {
                int din = dz + kd - 1;
                if (din < 0 || din >= Din) continue;
                for (int khr = 0; khr < 3; ++khr) {
                    int hin0 = h0 + khr - 1;            // -1..128
                    int v0 = (hin0 >= 0) ? 1 : 0;
                    int v1 = (hin0 + 1 <= 127) ? 1 : 0;
                    for (int cc = 0; cc < CC; ++cc) {
                        int wbase = ((kd * 3 + khr) * 3) * CC + cc;
                        s_din[n] = din;
                        s_aux[n] = (hin0 + 1) | (v0 << 8) | (v1 << 9) |
                                   (cc << 10) | (wbase << 14);
                        ++n;
                    }
                }
            }
        } else {
            for (int kd = 0; kd < 3; ++kd) {
                s_din[n] = 2 * dz + kd;
                s_aux[n] = (h0 + 1) | (1 << 8) | (1 << 9) | (kd << 14);
                ++n;
            }
        }
        s_n = n;
    }
    if (OMASK && tid < 256)
        s_mask[tid] = omask[((size_t)dz * 128 + h0 + (tid >> 7)) * 128 + (tid & 127)];
    __syncthreads();
    const int nch = s_n;

    // A ldmatrix addressing (stored row = m + kw for K333 halo; = m for down)
    u32 a_rowk[KW], a_sxk[KW];
    {
        int r = warp_m * 16 + (lane & 7) + ((lane >> 3) & 1) * 8;
        #pragma unroll
        for (int kw = 0; kw < KW; ++kw) {
            a_rowk[kw] = (u32)(r + kw) * 128;
            a_sxk[kw] = (u32)((r + kw) & 7) << 4;
        }
    }
    const u32 a_c = (u32)(lane >> 4) * 16;

    u32 b_row[2], b_sx[2];
    #pragma unroll
    for (int nh = 0; nh < 2; ++nh) {
        int rown = warp_n * 32 + nh * 16 + (lane & 7) + (lane >> 4) * 8;
        b_row[nh] = (u32)rown * 128;
        b_sx[nh] = (u32)(rown & 7) << 4;
    }
    const u32 b_c = (u32)((lane >> 3) & 1) * 16;

    float acc[2][4][4];
    #pragma unroll
    for (int tl = 0; tl < 2; ++tl)
        #pragma unroll
        for (int nt = 0; nt < 4; ++nt)
            #pragma unroll
            for (int q = 0; q < 4; ++q) acc[tl][nt][q] = 0.0f;

    // ---- staging ----
    auto stage = [&](int i, int buf) {
        const int din = s_din[i];
        const int aux = s_aux[i];
        const int hin0 = (aux & 255) - 1;
        const int v0 = (aux >> 8) & 1;
        const int v1 = (aux >> 9) & 1;
        const int cc = (aux >> 10) & 15;
        const int wb = aux >> 14;
        const u32 base = smem_base + (u32)buf * STAGEB;
        #pragma unroll 1
        for (int t = tid; t < 2 * AE; t += 512) {
            int tl = (t >= AE) ? 1 : 0;
            int u = t - tl * AE;
            int row = u >> 3, seg = u & 7;
            int win = K333 ? row - 1 : row;
            bool valid = (tl ? v1 : v0) && (!K333 || (unsigned)win < 128u);
            int hin = hin0 + tl;
            const char* src = (const char*)(in +
                (((size_t)din * 128 + (valid ? hin : 0)) * 128 +
                 (valid ? win : 0)) * CITOT + cc * 64) + seg * 16;
            cp_async16(base + tl * A_SPLIT + swz(row * 128 + seg * 16), src, valid);
        }
        #pragma unroll 1
        for (int t = tid; t < KW * 512; t += 512) {
            int kw = t >> 9, idx = t & 511;
            const char* src = (const char*)(wt +
                (size_t)(wb + kw * CC) * 4096) + idx * 16;
            cp_async16(base + STAGE_A + kw * 8192 + idx * 16, src, true);
        }
        cp_commit();
    };

    stage(0, 0);
    for (int i = 0; i < nch; ++i) {
        const int buf = i & 1;
        if (i + 1 < nch) { stage(i + 1, buf ^ 1); cp_wait<1>(); }
        else             { cp_wait<0>(); }
        __syncthreads();

        const u32 ab = smem_base + (u32)buf * STAGEB;
        const u32 bb = ab + STAGE_A;

        #pragma unroll
        for (int kw = 0; kw < KW; ++kw) {
            const u32 bhi = bb + kw * 8192;
            #pragma unroll
            for (int k16 = 0; k16 < 4; ++k16) {
                const u32 ko = k16 * 32;
                const u32 aoff = a_rowk[kw] + ((a_c + ko) ^ a_sxk[kw]);
                u32 A0[4], A1[4];
                LDMX4(A0[0], A0[1], A0[2], A0[3], ab + aoff);
                LDMX4(A1[0], A1[1], A1[2], A1[3], ab + A_SPLIT + aoff);
                u32 B0[4][2];
                #pragma unroll
                for (int nh = 0; nh < 2; ++nh) {
                    const u32 boff = b_row[nh] + ((b_c + ko) ^ b_sx[nh]);
                    LDMX4(B0[2*nh][0], B0[2*nh][1], B0[2*nh+1][0], B0[2*nh+1][1],
                          bhi + boff);
                }
                #pragma unroll
                for (int nt = 0; nt < 4; ++nt) {
                    mma_f16(acc[0][nt], A0, B0[nt]);
                    mma_f16(acc[1][nt], A1, B0[nt]);
                }
            }
        }
        __syncthreads();
    }

    // ---- epilogue ----
    const int g = lane >> 2, tg = lane & 3;
    #pragma unroll
    for (int tl = 0; tl < 2; ++tl) {
        const int h = h0 + tl;
        #pragma unroll
        for (int half = 0; half < 2; ++half) {
            const int m = warp_m * 16 + g + half * 8;
            const float mv = OMASK ? s_mask[tl * 128 + m] : 1.0f;
            const size_t row = ((size_t)dz * 128 + h) * 128 + m;
            #pragma unroll
            for (int nt = 0; nt < 4; ++nt) {
                const int n0 = warp_n * 32 + nt * 8 + tg * 2;
                const int q0 = half * 2;
                float v0 = fmaxf(acc[tl][nt][q0] * mv, 0.0f);
                float v1 = fmaxf(acc[tl][nt][q0 + 1] * mv, 0.0f);
                if (FP32OUT) {
                    out_f32[((size_t)n0 * Dout + dz) * HW + h * 128 + m] = v0;
                    out_f32[((size_t)(n0 + 1) * Dout + dz) * HW + h * 128 + m] = v1;
                } else {
                    __half2 hv(__float2half_rn(v0), __float2half_rn(v1));
                    *(u32*)(out + row * 64 + n0) = *(u32*)&hv;
                }
            }
        }
    }
}

#define SMEM_SUBM (2 * (2 * 16896 + 3 * 8192))   // 116736
#define SMEM_DOWN (2 * (2 * 16384 + 1 * 8192))   // 81920

// ============================================================================
extern "C" void kernel_launch(void* const* d_in, const int* in_sizes, int n_in,
                              void* d_out, int out_size)
{
    const float* feat = (const float*)d_in[0];
    const float* mask = (const float*)d_in[1];
    const float* W0   = (const float*)d_in[2];
    const float* Wd1  = (const float*)d_in[3];
    const float* W1a  = (const float*)d_in[4];
    const float* W1b  = (const float*)d_in[5];
    const float* Wd2  = (const float*)d_in[6];
    float* out = (float*)d_out;

    void* p;
    #define SYM(v, s) cudaGetSymbolAddress(&p, s); auto* v = (decltype(&s[0]))p;
    SYM(x0, g_x0) SYM(x1, g_x1) SYM(x2, g_x2) SYM(x3, g_x3)
    SYM(m0, g_m0) SYM(m2, g_m2)
    SYM(b0, g_B0) SYM(b1a, g_B1a) SYM(b1b, g_B1b)
    SYM(bd1, g_Bd1) SYM(bd2, g_Bd2)
    #undef SYM

    cudaFuncSetAttribute(conv_mma_kernel<2, true, true, false>,
                         cudaFuncAttributeMaxDynamicSharedMemorySize, SMEM_SUBM);
    cudaFuncSetAttribute(conv_mma_kernel<1, true, true, false>,
                         cudaFuncAttributeMaxDynamicSharedMemorySize, SMEM_SUBM);
    cudaFuncSetAttribute(conv_mma_kernel<1, false, false, false>,
                         cudaFuncAttributeMaxDynamicSharedMemorySize, SMEM_DOWN);
    cudaFuncSetAttribute(conv_mma_kernel<1, false, false, true>,
                         cudaFuncAttributeMaxDynamicSharedMemorySize, SMEM_DOWN);

    prep_weights<<<264, 256>>>(W0, Wd1, W1a, W1b, Wd2, mask);
    conv0_pre<<<dim3(128, 41), 256>>>(feat, mask);

    // conv0: 128->64, 3x3x3 SAME, output masked by m0 (input pre-masked)
    conv_mma_kernel<2, true, true, false><<<dim3(64, 41), 512, SMEM_SUBM>>>(
        x0, b0, m0, x1, nullptr, 41, 41);
    // down1: (3,1,1)/stride(2,1,1), relu
    conv_mma_kernel<1, false, false, false><<<dim3(64, 20), 512, SMEM_DOWN>>>(
        x1, bd1, nullptr, x2, nullptr, 41, 20);
    // subm1a / subm1b: 3x3x3 SAME, output masked by m2
    conv_mma_kernel<1, true, true, false><<<dim3(64, 20), 512, SMEM_SUBM>>>(
        x2, b1a, m2, x3, nullptr, 20, 20);
    conv_mma_kernel<1, true, true, false><<<dim3(64, 20), 512, SMEM_SUBM>>>(
        x3, b1b, m2, x1, nullptr, 20, 20);
    // down2 -> fp32 NCDHW output
    conv_mma_kernel<1, false, false, true><<<dim3(64, 9), 512, SMEM_DOWN>>>(
        x1, bd2, nullptr, nullptr, out, 20, 9);
}

// round 12
// speedup vs baseline: 2.6703x; 1.0724x over previous
#include <cuda_runtime.h>
#include <cuda_fp16.h>
#include <cstdint>

typedef unsigned int u32;
typedef unsigned long long u64;

#define HW 16384  // 128*128

// ============================================================================
// Static device scratch — activations single fp16, channels-last [d][h][w][ci]
// ============================================================================
__device__ __align__(16) __half g_x0[41 * HW * 128];
__device__ __align__(16) __half g_x1[41 * HW * 64];
__device__ __align__(16) __half g_x2[20 * HW * 64];
__device__ __align__(16) __half g_x3[20 * HW * 64];
__device__ float g_m0[41 * HW];
__device__ float g_m2[20 * HW];
// Weights: per-chunk [64 co][64 ci] fp16, PRE-SWIZZLED (SW128 XOR)
__device__ __align__(16) __half g_B0[54 * 4096];
__device__ __align__(16) __half g_B1a[27 * 4096];
__device__ __align__(16) __half g_B1b[27 * 4096];
__device__ __align__(16) __half g_Bd1[3 * 4096];
__device__ __align__(16) __half g_Bd2[3 * 4096];

// ============================================================================
// PTX helpers
// ============================================================================
__device__ __forceinline__ u32 smem_u32(const void* p) {
    u32 a;
    asm("{ .reg .u64 t; cvta.to.shared.u64 t, %1; cvt.u32.u64 %0, t; }"
        : "=r"(a) : "l"(p));
    return a;
}
__device__ __forceinline__ void cp_async16(u32 dst, const void* src, bool valid) {
    int sz = valid ? 16 : 0;
    asm volatile("cp.async.cg.shared.global [%0], [%1], 16, %2;"
                 :: "r"(dst), "l"(src), "r"(sz) : "memory");
}
__device__ __forceinline__ void cp_commit() {
    asm volatile("cp.async.commit_group;" ::: "memory");
}
template <int N>
__device__ __forceinline__ void cp_wait() {
    asm volatile("cp.async.wait_group %0;" :: "n"(N) : "memory");
}
#define LDMX4(r0, r1, r2, r3, addr) \
    asm volatile("ldmatrix.sync.aligned.m8n8.x4.shared.b16 {%0,%1,%2,%3}, [%4];" \
                 : "=r"(r0), "=r"(r1), "=r"(r2), "=r"(r3) : "r"(addr))

__device__ __forceinline__ void mma_f16(float* c, const u32* a, const u32* b) {
    asm volatile(
        "mma.sync.aligned.m16n8k16.row.col.f32.f16.f16.f32 "
        "{%0,%1,%2,%3}, {%4,%5,%6,%7}, {%8,%9}, {%0,%1,%2,%3};"
        : "+f"(c[0]), "+f"(c[1]), "+f"(c[2]), "+f"(c[3])
        : "r"(a[0]), "r"(a[1]), "r"(a[2]), "r"(a[3]), "r"(b[0]), "r"(b[1]));
}

__device__ __forceinline__ int swidx(int co, int ci) {
    int ub = co * 128 + (ci >> 3) * 16;
    int sw = ub ^ ((ub >> 3) & 0x70);
    return (sw >> 1) + (ci & 7);
}
__device__ __forceinline__ u32 swz(u32 b) { return b ^ ((b >> 3) & 0x70); }

// ============================================================================
// Prep kernels
// ============================================================================
__global__ void prep_weights(const float* __restrict__ W0,
                             const float* __restrict__ Wd1,
                             const float* __restrict__ W1a,
                             const float* __restrict__ W1b,
                             const float* __restrict__ Wd2,
                             const float* __restrict__ mask)
{
    const int gid = blockIdx.x * blockDim.x + threadIdx.x;
    const int gs = gridDim.x * blockDim.x;

    for (int i = gid; i < 54 * 4096; i += gs) {
        int chunk = i >> 12, r = i & 4095, co = r >> 6, ci = r & 63;
        int cc = chunk & 1, tap = chunk >> 1;
        int kw = tap % 3, kh = (tap / 3) % 3, kd = tap / 9;
        float v = W0[(size_t)(co * 128 + cc * 64 + ci) * 27 + kd * 9 + kh * 3 + kw];
        g_B0[chunk * 4096 + swidx(co, ci)] = __float2half_rn(v);
    }
    for (int i = gid; i < 27 * 4096; i += gs) {
        int chunk = i >> 12, r = i & 4095, co = r >> 6, ci = r & 63;
        int kw = chunk % 3, kh = (chunk / 3) % 3, kd = chunk / 9;
        size_t src = (size_t)(co * 64 + ci) * 27 + kd * 9 + kh * 3 + kw;
        int dst = chunk * 4096 + swidx(co, ci);
        g_B1a[dst] = __float2half_rn(W1a[src]);
        g_B1b[dst] = __float2half_rn(W1b[src]);
    }
    for (int i = gid; i < 3 * 4096; i += gs) {
        int chunk = i >> 12, r = i & 4095, co = r >> 6, ci = r & 63;
        size_t src = (size_t)(co * 64 + ci) * 3 + chunk;
        int dst = chunk * 4096 + swidx(co, ci);
        g_Bd1[dst] = __float2half_rn(Wd1[src]);
        g_Bd2[dst] = __float2half_rn(Wd2[src]);
    }
    for (int i = gid; i < 20 * HW; i += gs) {
        int dp = i >> 14, r = i & 16383;
        float a = mask[(size_t)(2 * dp) * HW + r];
        float b = mask[(size_t)(2 * dp + 1) * HW + r];
        float c = mask[(size_t)(2 * dp + 2) * HW + r];
        g_m2[i] = (fmaxf(a, fmaxf(b, c)) > 0.5f) ? 1.0f : 0.0f;
    }
}

__global__ void __launch_bounds__(256) conv0_pre(const float* __restrict__ feat,
                                                 const float* __restrict__ mask)
{
    const int h = blockIdx.x, d = blockIdx.y;
    const int tid = threadIdx.x;
    __shared__ float t[32][129];
    __shared__ float mrow[128];

    const size_t row0 = ((size_t)d * 128 + h) * 128;
    if (tid < 128) {
        float mv = mask[row0 + tid] > 0.5f ? 1.0f : 0.0f;
        mrow[tid] = mv;
        g_m0[row0 + tid] = mv;
    }
    __syncthreads();

    for (int cc = 0; cc < 4; ++cc) {
        #pragma unroll 1
        for (int i = tid; i < 32 * 128; i += 256) {
            int ci = i >> 7, w = i & 127;
            t[ci][w] = feat[((size_t)(cc * 32 + ci) * 41 + d) * HW + h * 128 + w];
        }
        __syncthreads();
        #pragma unroll 1
        for (int i = tid; i < 128 * 16; i += 256) {
            int w = i >> 4, p = i & 15;
            float mv = mrow[w];
            float v0 = t[p * 2][w] * mv;
            float v1 = t[p * 2 + 1][w] * mv;
            __half2 hv(__float2half_rn(v0), __float2half_rn(v1));
            size_t base = (row0 + w) * 128 + cc * 32;
            *(__half2*)(g_x0 + base + p * 2) = hv;
        }
        __syncthreads();
    }
}

// ============================================================================
// h-block implicit-GEMM conv (mma.sync fp16, single-term A·W).
// CTA = TL adjacent output h rows at one dz: per stage (kd, kh_rel[, cc]) the
// SAME B tap serves all TL rows (A tiles at hin0..hin0+TL-1).
// 512 threads: warp_m = wid&7 (m16, w dim), warp_n = wid>>3 (n32, cout).
// ============================================================================
template <int CC, int TL, bool K333, bool OMASK, bool FP32OUT>
__global__ void __launch_bounds__(512)
conv_mma_kernel(const __half* __restrict__ in,
                const __half* __restrict__ wt,
                const float* __restrict__ omask,
                __half* __restrict__ out,
                float* __restrict__ out_f32,
                int Din, int Dout)
{
    constexpr int KW = K333 ? 3 : 1;
    constexpr int AROWS = K333 ? 130 : 128;
    constexpr int AE = AROWS * 8;                  // 16B segs per A tile
    constexpr int A_SPLIT = K333 ? 16896 : 16384;  // one A tile, padded
    constexpr int STAGE_A = TL * A_SPLIT;
    constexpr int STAGE_B = KW * 8192;
    constexpr int STAGEB = STAGE_A + STAGE_B;

    extern __shared__ char smem[];
    const u32 smem_base = smem_u32(smem);
    const int tid = threadIdx.x;
    const int wid = tid >> 5;
    const int lane = tid & 31;
    const int h0 = blockIdx.x * TL;
    const int dz = blockIdx.y;
    const int CITOT = CC * 64;
    const int warp_m = wid & 7;
    const int warp_n = wid >> 3;

    __shared__ int s_din[18];
    __shared__ int s_aux[18];   // (hin0+1) | cc<<8 | wbase<<12
    __shared__ int s_n;
    __shared__ float s_mask[TL * 128];

    if (tid == 0) {
        int n = 0;
        if (K333) {
            for (int kd = 0; kd < 3; ++kd) {
                int din = dz + kd - 1;
                if (din < 0 || din >= Din) continue;
                for (int khr = 0; khr < 3; ++khr) {
                    int hin0 = h0 + khr - 1;            // -1..126
                    for (int cc = 0; cc < CC; ++cc) {
                        int wbase = ((kd * 3 + khr) * 3) * CC + cc;
                        s_din[n] = din;
                        s_aux[n] = (hin0 + 1) | (cc << 8) | (wbase << 12);
                        ++n;
                    }
                }
            }
        } else {
            for (int kd = 0; kd < 3; ++kd) {
                s_din[n] = 2 * dz + kd;
                s_aux[n] = (h0 + 1) | (kd << 12);
                ++n;
            }
        }
        s_n = n;
    }
    if (OMASK) {
        #pragma unroll
        for (int t = tid; t < TL * 128; t += 512)
            s_mask[t] = omask[((size_t)dz * 128 + h0 + (t >> 7)) * 128 + (t & 127)];
    }
    __syncthreads();
    const int nch = s_n;

    // A ldmatrix addressing (stored row = m + kw for K333 halo; = m for down)
    u32 a_rowk[KW], a_sxk[KW];
    {
        int r = warp_m * 16 + (lane & 7) + ((lane >> 3) & 1) * 8;
        #pragma unroll
        for (int kw = 0; kw < KW; ++kw) {
            a_rowk[kw] = (u32)(r + kw) * 128;
            a_sxk[kw] = (u32)((r + kw) & 7) << 4;
        }
    }
    const u32 a_c = (u32)(lane >> 4) * 16;

    u32 b_row[2], b_sx[2];
    #pragma unroll
    for (int nh = 0; nh < 2; ++nh) {
        int rown = warp_n * 32 + nh * 16 + (lane & 7) + (lane >> 4) * 8;
        b_row[nh] = (u32)rown * 128;
        b_sx[nh] = (u32)(rown & 7) << 4;
    }
    const u32 b_c = (u32)((lane >> 3) & 1) * 16;

    float acc[TL][4][4];
    #pragma unroll
    for (int tl = 0; tl < TL; ++tl)
        #pragma unroll
        for (int nt = 0; nt < 4; ++nt)
            #pragma unroll
            for (int q = 0; q < 4; ++q) acc[tl][nt][q] = 0.0f;

    // ---- staging ----
    auto stage = [&](int i, int buf) {
        const int din = s_din[i];
        const int aux = s_aux[i];
        const int hin0 = (aux & 255) - 1;
        const int cc = (aux >> 8) & 15;
        const int wb = aux >> 12;
        const u32 base = smem_base + (u32)buf * STAGEB;
        #pragma unroll
        for (int tl = 0; tl < TL; ++tl) {
            const int hin = hin0 + tl;
            const bool hok = (unsigned)hin < 128u;
            #pragma unroll 1
            for (int t = tid; t < AE; t += 512) {
                int row = t >> 3, seg = t & 7;
                int win = K333 ? row - 1 : row;
                bool valid = hok && (!K333 || (unsigned)win < 128u);
                const char* src = (const char*)(in +
                    (((size_t)din * 128 + (valid ? hin : 0)) * 128 +
                     (valid ? win : 0)) * CITOT + cc * 64) + seg * 16;
                cp_async16(base + tl * A_SPLIT + swz(row * 128 + seg * 16), src, valid);
            }
        }
        #pragma unroll 1
        for (int t = tid; t < KW * 512; t += 512) {
            int kw = t >> 9, idx = t & 511;
            const char* src = (const char*)(wt +
                (size_t)(wb + kw * CC) * 4096) + idx * 16;
            cp_async16(base + STAGE_A + kw * 8192 + idx * 16, src, true);
        }
        cp_commit();
    };

    stage(0, 0);
    for (int i = 0; i < nch; ++i) {
        const int buf = i & 1;
        if (i + 1 < nch) { stage(i + 1, buf ^ 1); cp_wait<1>(); }
        else             { cp_wait<0>(); }
        __syncthreads();

        const u32 ab = smem_base + (u32)buf * STAGEB;
        const u32 bb = ab + STAGE_A;

        #pragma unroll
        for (int kw = 0; kw < KW; ++kw) {
            const u32 bhi = bb + kw * 8192;
            #pragma unroll
            for (int k16 = 0; k16 < 4; ++k16) {
                const u32 ko = k16 * 32;
                const u32 aoff = a_rowk[kw] + ((a_c + ko) ^ a_sxk[kw]);
                u32 A[TL][4];
                #pragma unroll
                for (int tl = 0; tl < TL; ++tl)
                    LDMX4(A[tl][0], A[tl][1], A[tl][2], A[tl][3],
                          ab + tl * A_SPLIT + aoff);
                u32 B0[4][2];
                #pragma unroll
                for (int nh = 0; nh < 2; ++nh) {
                    const u32 boff = b_row[nh] + ((b_c + ko) ^ b_sx[nh]);
                    LDMX4(B0[2*nh][0], B0[2*nh][1], B0[2*nh+1][0], B0[2*nh+1][1],
                          bhi + boff);
                }
                #pragma unroll
                for (int nt = 0; nt < 4; ++nt)
                    #pragma unroll
                    for (int tl = 0; tl < TL; ++tl)
                        mma_f16(acc[tl][nt], A[tl], B0[nt]);
            }
        }
        __syncthreads();
    }

    // ---- epilogue ----
    const int g = lane >> 2, tg = lane & 3;
    #pragma unroll
    for (int tl = 0; tl < TL; ++tl) {
        const int h = h0 + tl;
        #pragma unroll
        for (int half = 0; half < 2; ++half) {
            const int m = warp_m * 16 + g + half * 8;
            const float mv = OMASK ? s_mask[tl * 128 + m] : 1.0f;
            const size_t row = ((size_t)dz * 128 + h) * 128 + m;
            #pragma unroll
            for (int nt = 0; nt < 4; ++nt) {
                const int n0 = warp_n * 32 + nt * 8 + tg * 2;
                const int q0 = half * 2;
                float v0 = fmaxf(acc[tl][nt][q0] * mv, 0.0f);
                float v1 = fmaxf(acc[tl][nt][q0 + 1] * mv, 0.0f);
                if (FP32OUT) {
                    out_f32[((size_t)n0 * Dout + dz) * HW + h * 128 + m] = v0;
                    out_f32[((size_t)(n0 + 1) * Dout + dz) * HW + h * 128 + m] = v1;
                } else {
                    __half2 hv(__float2half_rn(v0), __float2half_rn(v1));
                    *(u32*)(out + row * 64 + n0) = *(u32*)&hv;
                }
            }
        }
    }
}

#define SMEM_SUBM (2 * (4 * 16896 + 3 * 8192))   // 184320 (TL=4)
#define SMEM_DOWN (2 * (2 * 16384 + 1 * 8192))   // 81920  (TL=2)

// ============================================================================
extern "C" void kernel_launch(void* const* d_in, const int* in_sizes, int n_in,
                              void* d_out, int out_size)
{
    const float* feat = (const float*)d_in[0];
    const float* mask = (const float*)d_in[1];
    const float* W0   = (const float*)d_in[2];
    const float* Wd1  = (const float*)d_in[3];
    const float* W1a  = (const float*)d_in[4];
    const float* W1b  = (const float*)d_in[5];
    const float* Wd2  = (const float*)d_in[6];
    float* out = (float*)d_out;

    void* p;
    #define SYM(v, s) cudaGetSymbolAddress(&p, s); auto* v = (decltype(&s[0]))p;
    SYM(x0, g_x0) SYM(x1, g_x1) SYM(x2, g_x2) SYM(x3, g_x3)
    SYM(m0, g_m0) SYM(m2, g_m2)
    SYM(b0, g_B0) SYM(b1a, g_B1a) SYM(b1b, g_B1b)
    SYM(bd1, g_Bd1) SYM(bd2, g_Bd2)
    #undef SYM

    cudaFuncSetAttribute(conv_mma_kernel<2, 4, true, true, false>,
                         cudaFuncAttributeMaxDynamicSharedMemorySize, SMEM_SUBM);
    cudaFuncSetAttribute(conv_mma_kernel<1, 4, true, true, false>,
                         cudaFuncAttributeMaxDynamicSharedMemorySize, SMEM_SUBM);
    cudaFuncSetAttribute(conv_mma_kernel<1, 2, false, false, false>,
                         cudaFuncAttributeMaxDynamicSharedMemorySize, SMEM_DOWN);
    cudaFuncSetAttribute(conv_mma_kernel<1, 2, false, false, true>,
                         cudaFuncAttributeMaxDynamicSharedMemorySize, SMEM_DOWN);

    prep_weights<<<264, 256>>>(W0, Wd1, W1a, W1b, Wd2, mask);
    conv0_pre<<<dim3(128, 41), 256>>>(feat, mask);

    // conv0: 128->64, 3x3x3 SAME, output masked by m0 (input pre-masked)
    conv_mma_kernel<2, 4, true, true, false><<<dim3(32, 41), 512, SMEM_SUBM>>>(
        x0, b0, m0, x1, nullptr, 41, 41);
    // down1: (3,1,1)/stride(2,1,1), relu
    conv_mma_kernel<1, 2, false, false, false><<<dim3(64, 20), 512, SMEM_DOWN>>>(
        x1, bd1, nullptr, x2, nullptr, 41, 20);
    // subm1a / subm1b: 3x3x3 SAME, output masked by m2
    conv_mma_kernel<1, 4, true, true, false><<<dim3(32, 20), 512, SMEM_SUBM>>>(
        x2, b1a, m2, x3, nullptr, 20, 20);
    conv_mma_kernel<1, 4, true, true, false><<<dim3(32, 20), 512, SMEM_SUBM>>>(
        x3, b1b, m2, x1, nullptr, 20, 20);
    // down2 -> fp32 NCDHW output
    conv_mma_kernel<1, 2, false, false, true><<<dim3(64, 9), 512, SMEM_DOWN>>>(
        x1, bd2, nullptr, nullptr, out, 20, 9);
}

// round 13
// speedup vs baseline: 2.8396x; 1.0634x over previous
#include <cuda_runtime.h>
#include <cuda_fp16.h>
#include <cstdint>

typedef unsigned int u32;
typedef unsigned long long u64;

#define HW 16384  // 128*128

// ============================================================================
// Static device scratch — activations single fp16, channels-last [d][h][w][ci]
// ============================================================================
__device__ __align__(16) __half g_x0[41 * HW * 128];
__device__ __align__(16) __half g_x1[41 * HW * 64];
__device__ __align__(16) __half g_x2[20 * HW * 64];
__device__ __align__(16) __half g_x3[20 * HW * 64];
__device__ float g_m0[41 * HW];
__device__ float g_m2[20 * HW];
// Weights: per-chunk [64 co][64 ci] fp16, PRE-SWIZZLED (SW128 XOR)
__device__ __align__(16) __half g_B0[54 * 4096];
__device__ __align__(16) __half g_B1a[27 * 4096];
__device__ __align__(16) __half g_B1b[27 * 4096];
__device__ __align__(16) __half g_Bd1[3 * 4096];
__device__ __align__(16) __half g_Bd2[3 * 4096];

// ============================================================================
// PTX helpers
// ============================================================================
__device__ __forceinline__ u32 smem_u32(const void* p) {
    u32 a;
    asm("{ .reg .u64 t; cvta.to.shared.u64 t, %1; cvt.u32.u64 %0, t; }"
        : "=r"(a) : "l"(p));
    return a;
}
__device__ __forceinline__ void cp_async16(u32 dst, const void* src, bool valid) {
    int sz = valid ? 16 : 0;
    asm volatile("cp.async.cg.shared.global [%0], [%1], 16, %2;"
                 :: "r"(dst), "l"(src), "r"(sz) : "memory");
}
__device__ __forceinline__ void cp_commit() {
    asm volatile("cp.async.commit_group;" ::: "memory");
}
template <int N>
__device__ __forceinline__ void cp_wait() {
    asm volatile("cp.async.wait_group %0;" :: "n"(N) : "memory");
}
#define LDMX4(r0, r1, r2, r3, addr) \
    asm volatile("ldmatrix.sync.aligned.m8n8.x4.shared.b16 {%0,%1,%2,%3}, [%4];" \
                 : "=r"(r0), "=r"(r1), "=r"(r2), "=r"(r3) : "r"(addr))

__device__ __forceinline__ void mma_f16(float* c, const u32* a, const u32* b) {
    asm volatile(
        "mma.sync.aligned.m16n8k16.row.col.f32.f16.f16.f32 "
        "{%0,%1,%2,%3}, {%4,%5,%6,%7}, {%8,%9}, {%0,%1,%2,%3};"
        : "+f"(c[0]), "+f"(c[1]), "+f"(c[2]), "+f"(c[3])
        : "r"(a[0]), "r"(a[1]), "r"(a[2]), "r"(a[3]), "r"(b[0]), "r"(b[1]));
}

__device__ __forceinline__ int swidx(int co, int ci) {
    int ub = co * 128 + (ci >> 3) * 16;
    int sw = ub ^ ((ub >> 3) & 0x70);
    return (sw >> 1) + (ci & 7);
}
__device__ __forceinline__ u32 swz(u32 b) { return b ^ ((b >> 3) & 0x70); }

// ============================================================================
// Prep kernels
// ============================================================================
__global__ void prep_weights(const float* __restrict__ W0,
                             const float* __restrict__ Wd1,
                             const float* __restrict__ W1a,
                             const float* __restrict__ W1b,
                             const float* __restrict__ Wd2,
                             const float* __restrict__ mask)
{
    const int gid = blockIdx.x * blockDim.x + threadIdx.x;
    const int gs = gridDim.x * blockDim.x;

    for (int i = gid; i < 54 * 4096; i += gs) {
        int chunk = i >> 12, r = i & 4095, co = r >> 6, ci = r & 63;
        int cc = chunk & 1, tap = chunk >> 1;
        int kw = tap % 3, kh = (tap / 3) % 3, kd = tap / 9;
        float v = W0[(size_t)(co * 128 + cc * 64 + ci) * 27 + kd * 9 + kh * 3 + kw];
        g_B0[chunk * 4096 + swidx(co, ci)] = __float2half_rn(v);
    }
    for (int i = gid; i < 27 * 4096; i += gs) {
        int chunk = i >> 12, r = i & 4095, co = r >> 6, ci = r & 63;
        int kw = chunk % 3, kh = (chunk / 3) % 3, kd = chunk / 9;
        size_t src = (size_t)(co * 64 + ci) * 27 + kd * 9 + kh * 3 + kw;
        int dst = chunk * 4096 + swidx(co, ci);
        g_B1a[dst] = __float2half_rn(W1a[src]);
        g_B1b[dst] = __float2half_rn(W1b[src]);
    }
    for (int i = gid; i < 3 * 4096; i += gs) {
        int chunk = i >> 12, r = i & 4095, co = r >> 6, ci = r & 63;
        size_t src = (size_t)(co * 64 + ci) * 3 + chunk;
        int dst = chunk * 4096 + swidx(co, ci);
        g_Bd1[dst] = __float2half_rn(Wd1[src]);
        g_Bd2[dst] = __float2half_rn(Wd2[src]);
    }
    for (int i = gid; i < 20 * HW; i += gs) {
        int dp = i >> 14, r = i & 16383;
        float a = mask[(size_t)(2 * dp) * HW + r];
        float b = mask[(size_t)(2 * dp + 1) * HW + r];
        float c = mask[(size_t)(2 * dp + 2) * HW + r];
        g_m2[i] = (fmaxf(a, fmaxf(b, c)) > 0.5f) ? 1.0f : 0.0f;
    }
}

// conv0 input -> channels-last fp16, masked. 512 thr, 16B coalesced stores.
__global__ void __launch_bounds__(512) conv0_pre(const float* __restrict__ feat,
                                                 const float* __restrict__ mask)
{
    const int h = blockIdx.x, d = blockIdx.y;
    const int tid = threadIdx.x;
    __shared__ float t[64][129];
    __shared__ float mrow[128];

    const size_t row0 = ((size_t)d * 128 + h) * 128;
    if (tid < 128) {
        float mv = mask[row0 + tid] > 0.5f ? 1.0f : 0.0f;
        mrow[tid] = mv;
        g_m0[row0 + tid] = mv;
    }
    __syncthreads();

    for (int cc = 0; cc < 2; ++cc) {
        #pragma unroll 1
        for (int i = tid; i < 64 * 128; i += 512) {
            int ci = i >> 7, w = i & 127;
            t[ci][w] = feat[((size_t)(cc * 64 + ci) * 41 + d) * HW + h * 128 + w];
        }
        __syncthreads();
        #pragma unroll 1
        for (int i = tid; i < 128 * 8; i += 512) {
            int w = i >> 3, p = i & 7;
            float mv = mrow[w];
            u32 pk[4];
            #pragma unroll
            for (int j = 0; j < 4; ++j) {
                __half2 hv(__float2half_rn(t[p * 8 + 2 * j][w] * mv),
                           __float2half_rn(t[p * 8 + 2 * j + 1][w] * mv));
                pk[j] = *(u32*)&hv;
            }
            *(uint4*)(g_x0 + (row0 + w) * 128 + cc * 64 + p * 8) =
                make_uint4(pk[0], pk[1], pk[2], pk[3]);
        }
        __syncthreads();
    }
}

// ============================================================================
// h-block implicit-GEMM conv (mma.sync fp16, single-term A·W).
// CTA = TL adjacent output h rows at one dz; SAME B tap serves all TL rows.
// All stage-invariant cp.async addressing hoisted to registers before the loop.
// 512 threads: warp_m = wid&7 (m16, w dim), warp_n = wid>>3 (n32, cout).
// ============================================================================
template <int CC, int TL, bool K333, bool OMASK, bool FP32OUT>
__global__ void __launch_bounds__(512)
conv_mma_kernel(const __half* __restrict__ in,
                const __half* __restrict__ wt,
                const float* __restrict__ omask,
                __half* __restrict__ out,
                float* __restrict__ out_f32,
                int Din, int Dout)
{
    constexpr int KW = K333 ? 3 : 1;
    constexpr int AROWS = K333 ? 130 : 128;
    constexpr int AE = AROWS * 8;                  // 16B segs per A tile
    constexpr int A_SPLIT = K333 ? 16896 : 16384;  // one A tile, padded
    constexpr int STAGE_A = TL * A_SPLIT;
    constexpr int STAGE_B = KW * 8192;
    constexpr int STAGEB = STAGE_A + STAGE_B;
    constexpr int CITOT = CC * 64;
    constexpr int A_I = (AE + 511) / 512;          // 3 for K333, 2 for down

    extern __shared__ char smem[];
    const u32 smem_base = smem_u32(smem);
    const int tid = threadIdx.x;
    const int wid = tid >> 5;
    const int lane = tid & 31;
    const int h0 = blockIdx.x * TL;
    const int dz = blockIdx.y;
    const int warp_m = wid & 7;
    const int warp_n = wid >> 3;

    __shared__ int s_din[18];
    __shared__ int s_aux[18];   // (hin0+1) | cc<<8 | wbase<<12
    __shared__ int s_n;
    __shared__ float s_mask[TL * 128];

    if (tid == 0) {
        int n = 0;
        if (K333) {
            for (int kd = 0; kd < 3; ++kd) {
                int din = dz + kd - 1;
                if (din < 0 || din >= Din) continue;
                for (int khr = 0; khr < 3; ++khr) {
                    int hin0 = h0 + khr - 1;            // -1..126
                    for (int cc = 0; cc < CC; ++cc) {
                        int wbase = ((kd * 3 + khr) * 3) * CC + cc;
                        s_din[n] = din;
                        s_aux[n] = (hin0 + 1) | (cc << 8) | (wbase << 12);
                        ++n;
                    }
                }
            }
        } else {
            for (int kd = 0; kd < 3; ++kd) {
                s_din[n] = 2 * dz + kd;
                s_aux[n] = (h0 + 1) | (kd << 12);
                ++n;
            }
        }
        s_n = n;
    }
    if (OMASK) {
        #pragma unroll
        for (int t = tid; t < TL * 128; t += 512)
            s_mask[t] = omask[((size_t)dz * 128 + h0 + (t >> 7)) * 128 + (t & 127)];
    }
    __syncthreads();
    const int nch = s_n;

    // ---- hoisted per-thread staging geometry (stage-invariant) ----
    u32 a_dst[A_I];     // swizzled dst offset within one A tile
    int a_woff[A_I];    // byte offset from per-tl input row base
    bool a_wok[A_I];    // w-halo validity
    bool a_onk[A_I];    // thread participates in this iter
    #pragma unroll
    for (int k = 0; k < A_I; ++k) {
        int t = tid + k * 512;
        a_onk[k] = t < AE;
        int tt = a_onk[k] ? t : 0;
        int row = tt >> 3, seg = tt & 7;
        int win = K333 ? row - 1 : row;
        a_wok[k] = !K333 || (unsigned)win < 128u;
        a_dst[k] = swz(row * 128 + seg * 16);
        a_woff[k] = (a_wok[k] ? win : 0) * CITOT * 2 + seg * 16;
    }
    const u32 b_tid16 = (u32)tid * 16;

    // A ldmatrix addressing (stored row = m + kw for K333 halo; = m for down)
    u32 a_rowk[KW], a_sxk[KW];
    {
        int r = warp_m * 16 + (lane & 7) + ((lane >> 3) & 1) * 8;
        #pragma unroll
        for (int kw = 0; kw < KW; ++kw) {
            a_rowk[kw] = (u32)(r + kw) * 128;
            a_sxk[kw] = (u32)((r + kw) & 7) << 4;
        }
    }
    const u32 a_c = (u32)(lane >> 4) * 16;

    u32 b_row[2], b_sx[2];
    #pragma unroll
    for (int nh = 0; nh < 2; ++nh) {
        int rown = warp_n * 32 + nh * 16 + (lane & 7) + (lane >> 4) * 8;
        b_row[nh] = (u32)rown * 128;
        b_sx[nh] = (u32)(rown & 7) << 4;
    }
    const u32 b_c = (u32)((lane >> 3) & 1) * 16;

    float acc[TL][4][4];
    #pragma unroll
    for (int tl = 0; tl < TL; ++tl)
        #pragma unroll
        for (int nt = 0; nt < 4; ++nt)
            #pragma unroll
            for (int q = 0; q < 4; ++q) acc[tl][nt][q] = 0.0f;

    // ---- staging (addresses precomputed; per stage just base adds) ----
    auto stage = [&](int i, int buf) {
        const int din = s_din[i];
        const int aux = s_aux[i];
        const int hin0 = (aux & 255) - 1;
        const int cc = (aux >> 8) & 15;
        const int wb = aux >> 12;
        const u32 base = smem_base + (u32)buf * STAGEB;
        #pragma unroll
        for (int tl = 0; tl < TL; ++tl) {
            const int hin = hin0 + tl;
            const bool hok = !K333 || (unsigned)hin < 128u;
            const char* inb = (const char*)(in +
                (((size_t)din * 128 + (hok ? hin : 0)) * 128) * CITOT + cc * 64);
            const u32 adst = base + (u32)(tl * A_SPLIT);
            #pragma unroll
            for (int k = 0; k < A_I; ++k) {
                if (a_onk[k])
                    cp_async16(adst + a_dst[k], inb + a_woff[k], hok && a_wok[k]);
            }
        }
        const char* wsrc = (const char*)(wt + (size_t)wb * 4096) + b_tid16;
        #pragma unroll
        for (int kw = 0; kw < KW; ++kw)
            cp_async16(base + STAGE_A + kw * 8192 + b_tid16,
                       wsrc + (size_t)kw * CC * 8192, true);
        cp_commit();
    };

    stage(0, 0);
    for (int i = 0; i < nch; ++i) {
        const int buf = i & 1;
        if (i + 1 < nch) { stage(i + 1, buf ^ 1); cp_wait<1>(); }
        else             { cp_wait<0>(); }
        __syncthreads();

        const u32 ab = smem_base + (u32)buf * STAGEB;
        const u32 bb = ab + STAGE_A;

        #pragma unroll
        for (int kw = 0; kw < KW; ++kw) {
            const u32 bhi = bb + kw * 8192;
            #pragma unroll
            for (int k16 = 0; k16 < 4; ++k16) {
                const u32 ko = k16 * 32;
                const u32 aoff = a_rowk[kw] + ((a_c + ko) ^ a_sxk[kw]);
                u32 A[TL][4];
                #pragma unroll
                for (int tl = 0; tl < TL; ++tl)
                    LDMX4(A[tl][0], A[tl][1], A[tl][2], A[tl][3],
                          ab + tl * A_SPLIT + aoff);
                u32 B0[4][2];
                #pragma unroll
                for (int nh = 0; nh < 2; ++nh) {
                    const u32 boff = b_row[nh] + ((b_c + ko) ^ b_sx[nh]);
                    LDMX4(B0[2*nh][0], B0[2*nh][1], B0[2*nh+1][0], B0[2*nh+1][1],
                          bhi + boff);
                }
                #pragma unroll
                for (int nt = 0; nt < 4; ++nt)
                    #pragma unroll
                    for (int tl = 0; tl < TL; ++tl)
                        mma_f16(acc[tl][nt], A[tl], B0[nt]);
            }
        }
        __syncthreads();
    }

    // ---- epilogue ----
    const int g = lane >> 2, tg = lane & 3;
    #pragma unroll
    for (int tl = 0; tl < TL; ++tl) {
        const int h = h0 + tl;
        #pragma unroll
        for (int half = 0; half < 2; ++half) {
            const int m = warp_m * 16 + g + half * 8;
            const float mv = OMASK ? s_mask[tl * 128 + m] : 1.0f;
            const size_t row = ((size_t)dz * 128 + h) * 128 + m;
            #pragma unroll
            for (int nt = 0; nt < 4; ++nt) {
                const int n0 = warp_n * 32 + nt * 8 + tg * 2;
                const int q0 = half * 2;
                float v0 = fmaxf(acc[tl][nt][q0] * mv, 0.0f);
                float v1 = fmaxf(acc[tl][nt][q0 + 1] * mv, 0.0f);
                if (FP32OUT) {
                    out_f32[((size_t)n0 * Dout + dz) * HW + h * 128 + m] = v0;
                    out_f32[((size_t)(n0 + 1) * Dout + dz) * HW + h * 128 + m] = v1;
                } else {
                    __half2 hv(__float2half_rn(v0), __float2half_rn(v1));
                    *(u32*)(out + row * 64 + n0) = *(u32*)&hv;
                }
            }
        }
    }
}

#define SMEM_SUBM (2 * (4 * 16896 + 3 * 8192))   // 184320 (TL=4)
#define SMEM_DOWN (2 * (2 * 16384 + 1 * 8192))   // 81920  (TL=2)

// ============================================================================
extern "C" void kernel_launch(void* const* d_in, const int* in_sizes, int n_in,
                              void* d_out, int out_size)
{
    const float* feat = (const float*)d_in[0];
    const float* mask = (const float*)d_in[1];
    const float* W0   = (const float*)d_in[2];
    const float* Wd1  = (const float*)d_in[3];
    const float* W1a  = (const float*)d_in[4];
    const float* W1b  = (const float*)d_in[5];
    const float* Wd2  = (const float*)d_in[6];
    float* out = (float*)d_out;

    void* p;
    #define SYM(v, s) cudaGetSymbolAddress(&p, s); auto* v = (decltype(&s[0]))p;
    SYM(x0, g_x0) SYM(x1, g_x1) SYM(x2, g_x2) SYM(x3, g_x3)
    SYM(m0, g_m0) SYM(m2, g_m2)
    SYM(b0, g_B0) SYM(b1a, g_B1a) SYM(b1b, g_B1b)
    SYM(bd1, g_Bd1) SYM(bd2, g_Bd2)
    #undef SYM

    cudaFuncSetAttribute(conv_mma_kernel<2, 4, true, true, false>,
                         cudaFuncAttributeMaxDynamicSharedMemorySize, SMEM_SUBM);
    cudaFuncSetAttribute(conv_mma_kernel<1, 4, true, true, false>,
                         cudaFuncAttributeMaxDynamicSharedMemorySize, SMEM_SUBM);
    cudaFuncSetAttribute(conv_mma_kernel<1, 2, false, false, false>,
                         cudaFuncAttributeMaxDynamicSharedMemorySize, SMEM_DOWN);
    cudaFuncSetAttribute(conv_mma_kernel<1, 2, false, false, true>,
                         cudaFuncAttributeMaxDynamicSharedMemorySize, SMEM_DOWN);

    prep_weights<<<264, 256>>>(W0, Wd1, W1a, W1b, Wd2, mask);
    conv0_pre<<<dim3(128, 41), 512>>>(feat, mask);

    // conv0: 128->64, 3x3x3 SAME, output masked by m0 (input pre-masked)
    conv_mma_kernel<2, 4, true, true, false><<<dim3(32, 41), 512, SMEM_SUBM>>>(
        x0, b0, m0, x1, nullptr, 41, 41);
    // down1: (3,1,1)/stride(2,1,1), relu
    conv_mma_kernel<1, 2, false, false, false><<<dim3(64, 20), 512, SMEM_DOWN>>>(
        x1, bd1, nullptr, x2, nullptr, 41, 20);
    // subm1a / subm1b: 3x3x3 SAME, output masked by m2
    conv_mma_kernel<1, 4, true, true, false><<<dim3(32, 20), 512, SMEM_SUBM>>>(
        x2, b1a, m2, x3, nullptr, 20, 20);
    conv_mma_kernel<1, 4, true, true, false><<<dim3(32, 20), 512, SMEM_SUBM>>>(
        x3, b1b, m2, x1, nullptr, 20, 20);
    // down2 -> fp32 NCDHW output
    conv_mma_kernel<1, 2, false, false, true><<<dim3(64, 9), 512, SMEM_DOWN>>>(
        x1, bd2, nullptr, nullptr, out, 20, 9);
}